// round 9
// baseline (speedup 1.0000x reference)
#include <cuda_runtime.h>
#include <cuda_bf16.h>
#include <mma.h>
#include <cstdint>

using namespace nvcuda;

#define Bb 8
#define Ss 2048
#define Dd 1024
#define Mtot (Bb * Ss)

// ---------------------------------------------------------------------------
// Device-global scratch
// ---------------------------------------------------------------------------
__device__ float g_y[(size_t)Mtot * Dd];   // y = x @ Mt^T
__device__ float g_mt[(size_t)Dd * Dd];    // Mt = Wk @ Wq^T
__device__ float g_w[Mtot];                // v_t . Wo per token
__device__ float g_bt[Mtot];               // x_t . (Wk bq)
__device__ float g_u[Dd];                  // Wv @ Wo
__device__ float g_h[Dd];                  // Wk @ bq
__device__ float g_c;                      // bv . Wo

// ---------------------------------------------------------------------------
// prep kernels (validated)
// ---------------------------------------------------------------------------
__global__ void prep_c(const float* __restrict__ bv, const float* __restrict__ Wo)
{
    __shared__ float red[8];
    int tid = threadIdx.x;
    float4 a = ((const float4*)bv)[tid];
    float4 b = ((const float4*)Wo)[tid];
    float s = a.x * b.x + a.y * b.y + a.z * b.z + a.w * b.w;
    #pragma unroll
    for (int off = 16; off; off >>= 1) s += __shfl_xor_sync(0xffffffffu, s, off);
    if ((tid & 31) == 0) red[tid >> 5] = s;
    __syncthreads();
    if (tid < 8) {
        s = red[tid];
        #pragma unroll
        for (int off = 4; off; off >>= 1) s += __shfl_xor_sync(0xffu, s, off);
        if (tid == 0) g_c = s;
    }
}

__global__ void gemv_row(const float* __restrict__ A, const float* __restrict__ vec,
                         float* __restrict__ outv)
{
    __shared__ float red[8];
    int m = blockIdx.x;
    int tid = threadIdx.x;
    float4 a = ((const float4*)(A + (size_t)m * Dd))[tid];
    float4 u = ((const float4*)vec)[tid];
    float s = a.x * u.x + a.y * u.y + a.z * u.z + a.w * u.w;
    #pragma unroll
    for (int off = 16; off; off >>= 1) s += __shfl_xor_sync(0xffffffffu, s, off);
    if ((tid & 31) == 0) red[tid >> 5] = s;
    __syncthreads();
    if (tid < 8) {
        s = red[tid];
        #pragma unroll
        for (int off = 4; off; off >>= 1) s += __shfl_xor_sync(0xffu, s, off);
        if (tid == 0) outv[m] = s;
    }
}

__global__ void gemv_row2(const float* __restrict__ x)
{
    __shared__ float red1[8], red2[8];
    int m = blockIdx.x;
    int tid = threadIdx.x;
    float4 a = ((const float4*)(x + (size_t)m * Dd))[tid];
    float4 u = ((const float4*)g_u)[tid];
    float4 h = ((const float4*)g_h)[tid];
    float s1 = a.x * u.x + a.y * u.y + a.z * u.z + a.w * u.w;
    float s2 = a.x * h.x + a.y * h.y + a.z * h.z + a.w * h.w;
    #pragma unroll
    for (int off = 16; off; off >>= 1) {
        s1 += __shfl_xor_sync(0xffffffffu, s1, off);
        s2 += __shfl_xor_sync(0xffffffffu, s2, off);
    }
    if ((tid & 31) == 0) { red1[tid >> 5] = s1; red2[tid >> 5] = s2; }
    __syncthreads();
    if (tid < 8) {
        s1 = red1[tid]; s2 = red2[tid];
        #pragma unroll
        for (int off = 4; off; off >>= 1) {
            s1 += __shfl_xor_sync(0xffu, s1, off);
            s2 += __shfl_xor_sync(0xffu, s2, off);
        }
        if (tid == 0) { g_w[m] = s1 + g_c; g_bt[m] = s2; }
    }
}

// ---------------------------------------------------------------------------
// wmma machinery: CTA tile 128(m) x 256(n), 8 warps of 64x64, k-chunk 32.
// ---------------------------------------------------------------------------
#define TP_E 40                        // tile pitch, bf16 elements (80 B)
#define A_T_B (128 * 80)               // A tile bytes (10240)
#define B_T_B (256 * 80)               // B tile bytes (20480)
#define OFF_AL A_T_B
#define OFF_BH (2 * A_T_B)
#define OFF_BL (2 * A_T_B + B_T_B)
#define BUF_B  (2 * A_T_B + 2 * B_T_B) // 61440
#define BUFS_B (2 * BUF_B)             // 122880
#define STG_P  260                     // stage pitch, floats
#define STG_B  (128 * STG_P * 4)       // 133120
#define FL_WS  STG_B
#define FL_BT  (STG_B + 1024)
#define ABT_SMEM   STG_B
#define FLASH_SMEM (STG_B + 2048)

typedef wmma::fragment<wmma::matrix_a, 16, 16, 16, __nv_bfloat16, wmma::row_major> FragA;
typedef wmma::fragment<wmma::matrix_b, 16, 16, 16, __nv_bfloat16, wmma::col_major> FragB;
typedef wmma::fragment<wmma::accumulator, 16, 16, 16, float> FragC;

__device__ __forceinline__ void load16(float* v, const float* p) {
#pragma unroll
    for (int i = 0; i < 4; ++i) ((float4*)v)[i] = ((const float4*)p)[i];
}

__device__ __forceinline__ void split16_store(char* hi, char* lo, uint32_t off,
                                              const float* v) {
    alignas(16) __nv_bfloat16 h[16], l[16];
#pragma unroll
    for (int j = 0; j < 16; ++j) {
        float f = v[j];
        __nv_bfloat16 hh = __float2bfloat16(f);
        h[j] = hh;
        l[j] = __float2bfloat16(f - __bfloat162float(hh));
    }
    *(uint4*)(hi + off)      = ((const uint4*)h)[0];
    *(uint4*)(hi + off + 16) = ((const uint4*)h)[1];
    *(uint4*)(lo + off)      = ((const uint4*)l)[0];
    *(uint4*)(lo + off + 16) = ((const uint4*)l)[1];
}

// Load + split one 32-float k-slice for: A row ra, B rows rb0=ra, rb1=ra+128.
// srcA/srcB0/srcB1 already point at (row, half*16); col0 = kc*32.
__device__ __forceinline__ void stage_chunk(char* buf,
                                            const float* srcA, const float* srcB0,
                                            const float* srcB1, int col0,
                                            uint32_t soffA, uint32_t soffB0,
                                            uint32_t soffB1)
{
    float ra[16], rb0[16], rb1[16];
    load16(ra, srcA + col0);
    load16(rb0, srcB0 + col0);
    load16(rb1, srcB1 + col0);
    split16_store(buf, buf + OFF_AL, soffA, ra);
    split16_store(buf + OFF_BH, buf + OFF_BL, soffB0, rb0);
    split16_store(buf + OFF_BH, buf + OFF_BL, soffB1, rb1);
}

// One 32-k chunk, 3-split, warp tile 64(m) x 64(n). wm in 0..1, wn in 0..3.
__device__ __forceinline__ void mma_chunk64(const char* buf, int wm, int wn,
                                            FragC (&acc)[4][4])
{
    const __nv_bfloat16* tA  = (const __nv_bfloat16*)(buf);
    const __nv_bfloat16* tAl = (const __nv_bfloat16*)(buf + OFF_AL);
    const __nv_bfloat16* tB  = (const __nv_bfloat16*)(buf + OFF_BH);
    const __nv_bfloat16* tBl = (const __nv_bfloat16*)(buf + OFF_BL);
#pragma unroll
    for (int ks = 0; ks < 2; ++ks) {
        FragA ah[4], al[4];
#pragma unroll
        for (int mi = 0; mi < 4; ++mi) {
            int ro = (64 * wm + 16 * mi) * TP_E + ks * 16;
            wmma::load_matrix_sync(ah[mi], tA + ro, TP_E);
            wmma::load_matrix_sync(al[mi], tAl + ro, TP_E);
        }
#pragma unroll
        for (int pj = 0; pj < 4; ++pj) {
            int ro = (64 * wn + 16 * pj) * TP_E + ks * 16;
            FragB bh, bl;
            wmma::load_matrix_sync(bh, tB + ro, TP_E);
            wmma::load_matrix_sync(bl, tBl + ro, TP_E);
#pragma unroll
            for (int mi = 0; mi < 4; ++mi) {
                wmma::mma_sync(acc[mi][pj], ah[mi], bh, acc[mi][pj]);
                wmma::mma_sync(acc[mi][pj], ah[mi], bl, acc[mi][pj]);
                wmma::mma_sync(acc[mi][pj], al[mi], bh, acc[mi][pj]);
            }
        }
    }
}

__device__ __forceinline__ void store_stage(float* stage, int wm, int wn,
                                            FragC (&acc)[4][4])
{
#pragma unroll
    for (int mi = 0; mi < 4; ++mi)
#pragma unroll
        for (int pj = 0; pj < 4; ++pj)
            wmma::store_matrix_sync(
                stage + (size_t)(64 * wm + 16 * mi) * STG_P + 64 * wn + 16 * pj,
                acc[mi][pj], STG_P, wmma::mem_row_major);
}

// ---------------------------------------------------------------------------
// wmma A@B^T: C[m0+128, n0+256] = A[m0..,:] . B[n0..,:]^T   (256 threads)
// ---------------------------------------------------------------------------
__global__ void __launch_bounds__(256, 1)
wmma_abt(const float* __restrict__ A, const float* __restrict__ B,
         float* __restrict__ C)
{
    extern __shared__ char sm[];
    int tid = threadIdx.x;
    int wid = tid >> 5;
    int wm = wid & 1, wn = wid >> 1;
    int m0 = blockIdx.y * 128;
    int n0 = blockIdx.x * 256;

    float* stage = (float*)sm;

    int ra = tid >> 1;
    int half = tid & 1;
    uint32_t soffA  = (uint32_t)ra * 80 + half * 32;
    uint32_t soffB0 = soffA;
    uint32_t soffB1 = soffA + 128u * 80;
    const float* srcA  = A + (size_t)(m0 + ra) * Dd + half * 16;
    const float* srcB0 = B + (size_t)(n0 + ra) * Dd + half * 16;
    const float* srcB1 = B + (size_t)(n0 + 128 + ra) * Dd + half * 16;

    FragC acc[4][4];
#pragma unroll
    for (int mi = 0; mi < 4; ++mi)
#pragma unroll
        for (int pj = 0; pj < 4; ++pj)
            wmma::fill_fragment(acc[mi][pj], 0.f);

    stage_chunk(sm, srcA, srcB0, srcB1, 0, soffA, soffB0, soffB1);
    __syncthreads();

    const int NK = Dd / 32;
    for (int kc = 0; kc < NK; ++kc) {
        char* buf = sm + (size_t)(kc & 1) * BUF_B;
        if (kc + 1 < NK)
            stage_chunk(sm + (size_t)((kc + 1) & 1) * BUF_B,
                        srcA, srcB0, srcB1, (kc + 1) * 32,
                        soffA, soffB0, soffB1);
        mma_chunk64(buf, wm, wn, acc);
        __syncthreads();
    }

    store_stage(stage, wm, wn, acc);
    __syncthreads();

    int r = tid >> 1;
    int c0 = (tid & 1) * 128;
    const float* sr = stage + (size_t)r * STG_P + c0;
    float* cr = C + (size_t)(m0 + r) * Dd + n0 + c0;
#pragma unroll
    for (int j = 0; j < 32; ++j)
        ((float4*)cr)[j] = ((const float4*)sr)[j];
}

// ---------------------------------------------------------------------------
// wmma flash: scores = y . x^T + bt ; softmax ; rank-1 w.  (256 threads)
// q-block 128, t-block 256. grid (Ss/128, Bb).
// ---------------------------------------------------------------------------
__global__ void __launch_bounds__(256, 1)
wmma_flash(const float* __restrict__ x, const float* __restrict__ bo,
           float* __restrict__ out)
{
    extern __shared__ char sm[];
    int tid = threadIdx.x;
    int wid = tid >> 5;
    int wm = wid & 1, wn = wid >> 1;
    int b = blockIdx.y;
    int q0 = blockIdx.x * 128;

    float* stage = (float*)sm;
    float* ws  = (float*)(sm + FL_WS);
    float* bts = (float*)(sm + FL_BT);

    const float* qb = g_y + ((size_t)b * Ss + q0) * Dd;
    const float* kb = x + (size_t)b * Ss * Dd;
    const float bo0 = __ldg(bo);

    int ra = tid >> 1;
    int half = tid & 1;
    uint32_t soffA  = (uint32_t)ra * 80 + half * 32;
    uint32_t soffB1 = soffA + 128u * 80;
    const float* srcA = qb + (size_t)ra * Dd + half * 16;

    const int NK = Dd / 32;
    float rm = -1e30f, rl = 0.f, rc = 0.f;   // row = tid>>1, replicated in pair

    for (int t0 = 0; t0 < Ss; t0 += 256) {
        const float* srcB0 = kb + (size_t)(t0 + ra) * Dd + half * 16;
        const float* srcB1 = kb + (size_t)(t0 + 128 + ra) * Dd + half * 16;
        ws[tid]  = g_w[(size_t)b * Ss + t0 + tid];
        bts[tid] = g_bt[(size_t)b * Ss + t0 + tid];

        FragC acc[4][4];
#pragma unroll
        for (int mi = 0; mi < 4; ++mi)
#pragma unroll
            for (int pj = 0; pj < 4; ++pj)
                wmma::fill_fragment(acc[mi][pj], 0.f);

        stage_chunk(sm, srcA, srcB0, srcB1, 0, soffA, soffA, soffB1);
        __syncthreads();

        for (int kc = 0; kc < NK; ++kc) {
            char* buf = sm + (size_t)(kc & 1) * BUF_B;
            if (kc + 1 < NK)
                stage_chunk(sm + (size_t)((kc + 1) & 1) * BUF_B,
                            srcA, srcB0, srcB1, (kc + 1) * 32,
                            soffA, soffA, soffB1);
            mma_chunk64(buf, wm, wn, acc);
            __syncthreads();
        }

        store_stage(stage, wm, wn, acc);
        __syncthreads();

        // pair softmax: thread handles row=tid>>1, cols [half*128, +128)
        {
            int row = tid >> 1;
            const float4* rp = (const float4*)(stage + (size_t)row * STG_P + half * 128);
            const float4* btp = (const float4*)(bts + half * 128);
            float m = -1e30f;
#pragma unroll 8
            for (int j = 0; j < 32; ++j) {
                float4 s4 = rp[j];
                float4 b4 = btp[j];
                s4.x += b4.x; s4.y += b4.y; s4.z += b4.z; s4.w += b4.w;
                m = fmaxf(m, fmaxf(fmaxf(s4.x, s4.y), fmaxf(s4.z, s4.w)));
            }
            m = fmaxf(m, __shfl_xor_sync(0xffffffffu, m, 1));
            float nm = fmaxf(rm, m);
            float f = __expf(rm - nm);
            float tl = 0.f, ta = 0.f;
            const float4* wp = (const float4*)(ws + half * 128);
#pragma unroll 8
            for (int j = 0; j < 32; ++j) {
                float4 s4 = rp[j];
                float4 b4 = btp[j];
                float4 w4 = wp[j];
                float p0 = __expf(s4.x + b4.x - nm);
                float p1 = __expf(s4.y + b4.y - nm);
                float p2 = __expf(s4.z + b4.z - nm);
                float p3 = __expf(s4.w + b4.w - nm);
                tl += (p0 + p1) + (p2 + p3);
                ta += p0 * w4.x + p1 * w4.y + p2 * w4.z + p3 * w4.w;
            }
            tl += __shfl_xor_sync(0xffffffffu, tl, 1);
            ta += __shfl_xor_sync(0xffffffffu, ta, 1);
            rl = rl * f + tl;
            rc = rc * f + ta;
            rm = nm;
        }
        __syncthreads();
    }

    if ((tid & 1) == 0)
        out[(size_t)b * Ss + q0 + (tid >> 1)] = rc / rl + bo0;
}

// ---------------------------------------------------------------------------
extern "C" void kernel_launch(void* const* d_in, const int* in_sizes, int n_in,
                              void* d_out, int out_size)
{
    const float* x  = (const float*)d_in[0];
    const float* Wq = (const float*)d_in[1];
    const float* bq = (const float*)d_in[2];
    const float* Wk = (const float*)d_in[3];
    const float* bk = (const float*)d_in[4];
    const float* Wv = (const float*)d_in[5];
    const float* bv = (const float*)d_in[6];
    const float* Wo = (const float*)d_in[7];
    const float* bo = (const float*)d_in[8];
    float* out = (float*)d_out;
    (void)bk; (void)in_sizes; (void)n_in; (void)out_size;

    static bool attr_done = false;
    if (!attr_done) {
        cudaFuncSetAttribute(wmma_abt,
                             cudaFuncAttributeMaxDynamicSharedMemorySize, ABT_SMEM);
        cudaFuncSetAttribute(wmma_flash,
                             cudaFuncAttributeMaxDynamicSharedMemorySize, FLASH_SMEM);
        attr_done = true;
    }

    float* yq = nullptr; cudaGetSymbolAddress((void**)&yq, g_y);
    float* mt = nullptr; cudaGetSymbolAddress((void**)&mt, g_mt);
    float* uu = nullptr; cudaGetSymbolAddress((void**)&uu, g_u);
    float* hh = nullptr; cudaGetSymbolAddress((void**)&hh, g_h);

    // scalars + per-feature vectors
    prep_c<<<1, 256>>>(bv, Wo);
    gemv_row<<<Dd, 256>>>(Wv, Wo, uu);    // u = Wv @ Wo
    gemv_row<<<Dd, 256>>>(Wk, bq, hh);    // h = Wk @ bq
    gemv_row2<<<Mtot, 256>>>(x);          // w = x.u + c ; bt = x.h

    // Mt = Wk @ Wq^T, then y = x @ Mt^T
    {
        dim3 gm(Dd / 256, Dd / 128);
        wmma_abt<<<gm, 256, ABT_SMEM>>>(Wk, Wq, mt);
        dim3 gy(Dd / 256, Mtot / 128);
        wmma_abt<<<gy, 256, ABT_SMEM>>>(x, mt, yq);
    }

    // fused scores(y.x^T + bt) + softmax + rank-1 w reduction
    dim3 gf(Ss / 128, Bb);
    wmma_flash<<<gf, 256, FLASH_SMEM>>>(x, bo, out);
}

// round 10
// speedup vs baseline: 1.0956x; 1.0956x over previous
#include <cuda_runtime.h>
#include <cuda_bf16.h>
#include <mma.h>
#include <cstdint>

using namespace nvcuda;

#define Bb 8
#define Ss 2048
#define Dd 1024
#define Mtot (Bb * Ss)

// ---------------------------------------------------------------------------
// Device-global scratch
// ---------------------------------------------------------------------------
__device__ float g_y[(size_t)Mtot * Dd];   // y = x @ Mt^T
__device__ float g_mt[(size_t)Dd * Dd];    // Mt = Wk @ Wq^T
__device__ float g_w[Mtot];                // v_t . Wo per token
__device__ float g_bt[Mtot];               // x_t . (Wk bq)
__device__ float g_u[Dd];                  // Wv @ Wo
__device__ float g_h[Dd];                  // Wk @ bq
__device__ float g_c;                      // bv . Wo

// ---------------------------------------------------------------------------
// prep kernels (validated)
// ---------------------------------------------------------------------------
__global__ void prep_c(const float* __restrict__ bv, const float* __restrict__ Wo)
{
    __shared__ float red[8];
    int tid = threadIdx.x;
    float4 a = ((const float4*)bv)[tid];
    float4 b = ((const float4*)Wo)[tid];
    float s = a.x * b.x + a.y * b.y + a.z * b.z + a.w * b.w;
    #pragma unroll
    for (int off = 16; off; off >>= 1) s += __shfl_xor_sync(0xffffffffu, s, off);
    if ((tid & 31) == 0) red[tid >> 5] = s;
    __syncthreads();
    if (tid < 8) {
        s = red[tid];
        #pragma unroll
        for (int off = 4; off; off >>= 1) s += __shfl_xor_sync(0xffu, s, off);
        if (tid == 0) g_c = s;
    }
}

__global__ void gemv_row(const float* __restrict__ A, const float* __restrict__ vec,
                         float* __restrict__ outv)
{
    __shared__ float red[8];
    int m = blockIdx.x;
    int tid = threadIdx.x;
    float4 a = ((const float4*)(A + (size_t)m * Dd))[tid];
    float4 u = ((const float4*)vec)[tid];
    float s = a.x * u.x + a.y * u.y + a.z * u.z + a.w * u.w;
    #pragma unroll
    for (int off = 16; off; off >>= 1) s += __shfl_xor_sync(0xffffffffu, s, off);
    if ((tid & 31) == 0) red[tid >> 5] = s;
    __syncthreads();
    if (tid < 8) {
        s = red[tid];
        #pragma unroll
        for (int off = 4; off; off >>= 1) s += __shfl_xor_sync(0xffu, s, off);
        if (tid == 0) outv[m] = s;
    }
}

__global__ void gemv_row2(const float* __restrict__ x)
{
    __shared__ float red1[8], red2[8];
    int m = blockIdx.x;
    int tid = threadIdx.x;
    float4 a = ((const float4*)(x + (size_t)m * Dd))[tid];
    float4 u = ((const float4*)g_u)[tid];
    float4 h = ((const float4*)g_h)[tid];
    float s1 = a.x * u.x + a.y * u.y + a.z * u.z + a.w * u.w;
    float s2 = a.x * h.x + a.y * h.y + a.z * h.z + a.w * h.w;
    #pragma unroll
    for (int off = 16; off; off >>= 1) {
        s1 += __shfl_xor_sync(0xffffffffu, s1, off);
        s2 += __shfl_xor_sync(0xffffffffu, s2, off);
    }
    if ((tid & 31) == 0) { red1[tid >> 5] = s1; red2[tid >> 5] = s2; }
    __syncthreads();
    if (tid < 8) {
        s1 = red1[tid]; s2 = red2[tid];
        #pragma unroll
        for (int off = 4; off; off >>= 1) {
            s1 += __shfl_xor_sync(0xffu, s1, off);
            s2 += __shfl_xor_sync(0xffu, s2, off);
        }
        if (tid == 0) { g_w[m] = s1 + g_c; g_bt[m] = s2; }
    }
}

// ---------------------------------------------------------------------------
// wmma machinery: CTA tile 128(m) x 256(n), 8 warps of 64x64, k-chunk 32.
// ---------------------------------------------------------------------------
#define TP_E 40                        // tile pitch, bf16 elements (80 B)
#define A_T_B (128 * 80)               // A tile bytes (10240)
#define B_T_B (256 * 80)               // B tile bytes (20480)
#define OFF_AL A_T_B
#define OFF_BH (2 * A_T_B)
#define OFF_BL (2 * A_T_B + B_T_B)
#define BUF_B  (2 * A_T_B + 2 * B_T_B) // 61440
#define STG_P  260                     // stage pitch, floats
#define STG_B  (128 * STG_P * 4)       // 133120
#define FL_WS  STG_B
#define FL_BT  (STG_B + 1024)
#define ABT_SMEM   STG_B
#define FLASH_SMEM (STG_B + 2048)

typedef wmma::fragment<wmma::matrix_a, 16, 16, 16, __nv_bfloat16, wmma::row_major> FragA;
typedef wmma::fragment<wmma::matrix_b, 16, 16, 16, __nv_bfloat16, wmma::col_major> FragB;
typedef wmma::fragment<wmma::accumulator, 16, 16, 16, float> FragC;

__device__ __forceinline__ void load16(float* v, const float* p) {
#pragma unroll
    for (int i = 0; i < 4; ++i) ((float4*)v)[i] = ((const float4*)p)[i];
}

__device__ __forceinline__ void split16_store(char* hi, char* lo, uint32_t off,
                                              const float* v) {
    alignas(16) __nv_bfloat16 h[16], l[16];
#pragma unroll
    for (int j = 0; j < 16; ++j) {
        float f = v[j];
        __nv_bfloat16 hh = __float2bfloat16(f);
        h[j] = hh;
        l[j] = __float2bfloat16(f - __bfloat162float(hh));
    }
    *(uint4*)(hi + off)      = ((const uint4*)h)[0];
    *(uint4*)(hi + off + 16) = ((const uint4*)h)[1];
    *(uint4*)(lo + off)      = ((const uint4*)l)[0];
    *(uint4*)(lo + off + 16) = ((const uint4*)l)[1];
}

// store the three 16-float register slices into a chunk buffer
__device__ __forceinline__ void store_regs(char* buf, const float* ra,
                                           const float* rb0, const float* rb1,
                                           uint32_t soffA, uint32_t soffB0,
                                           uint32_t soffB1)
{
    split16_store(buf, buf + OFF_AL, soffA, ra);
    split16_store(buf + OFF_BH, buf + OFF_BL, soffB0, rb0);
    split16_store(buf + OFF_BH, buf + OFF_BL, soffB1, rb1);
}

// One 32-k chunk, 3-split, warp tile 64(m) x 64(n). wm in 0..1, wn in 0..3.
__device__ __forceinline__ void mma_chunk64(const char* buf, int wm, int wn,
                                            FragC (&acc)[4][4])
{
    const __nv_bfloat16* tA  = (const __nv_bfloat16*)(buf);
    const __nv_bfloat16* tAl = (const __nv_bfloat16*)(buf + OFF_AL);
    const __nv_bfloat16* tB  = (const __nv_bfloat16*)(buf + OFF_BH);
    const __nv_bfloat16* tBl = (const __nv_bfloat16*)(buf + OFF_BL);
#pragma unroll
    for (int ks = 0; ks < 2; ++ks) {
        FragA ah[4], al[4];
#pragma unroll
        for (int mi = 0; mi < 4; ++mi) {
            int ro = (64 * wm + 16 * mi) * TP_E + ks * 16;
            wmma::load_matrix_sync(ah[mi], tA + ro, TP_E);
            wmma::load_matrix_sync(al[mi], tAl + ro, TP_E);
        }
#pragma unroll
        for (int pj = 0; pj < 4; ++pj) {
            int ro = (64 * wn + 16 * pj) * TP_E + ks * 16;
            FragB bh, bl;
            wmma::load_matrix_sync(bh, tB + ro, TP_E);
            wmma::load_matrix_sync(bl, tBl + ro, TP_E);
#pragma unroll
            for (int mi = 0; mi < 4; ++mi) {
                wmma::mma_sync(acc[mi][pj], ah[mi], bh, acc[mi][pj]);
                wmma::mma_sync(acc[mi][pj], ah[mi], bl, acc[mi][pj]);
                wmma::mma_sync(acc[mi][pj], al[mi], bh, acc[mi][pj]);
            }
        }
    }
}

__device__ __forceinline__ void store_stage(float* stage, int wm, int wn,
                                            FragC (&acc)[4][4])
{
#pragma unroll
    for (int mi = 0; mi < 4; ++mi)
#pragma unroll
        for (int pj = 0; pj < 4; ++pj)
            wmma::store_matrix_sync(
                stage + (size_t)(64 * wm + 16 * mi) * STG_P + 64 * wn + 16 * pj,
                acc[mi][pj], STG_P, wmma::mem_row_major);
}

// ---------------------------------------------------------------------------
// wmma A@B^T: C[m0+128, n0+256] = A[m0..,:] . B[n0..,:]^T   (256 threads)
// Pipeline: LDG(next)->regs ; mma(cur) ; split_store(next) ; barrier.
// ---------------------------------------------------------------------------
__global__ void __launch_bounds__(256, 1)
wmma_abt(const float* __restrict__ A, const float* __restrict__ B,
         float* __restrict__ C)
{
    extern __shared__ char sm[];
    int tid = threadIdx.x;
    int wid = tid >> 5;
    int wm = wid & 1, wn = wid >> 1;
    int m0 = blockIdx.y * 128;
    int n0 = blockIdx.x * 256;

    float* stage = (float*)sm;

    int ra_ = tid >> 1;
    int half = tid & 1;
    uint32_t soffA  = (uint32_t)ra_ * 80 + half * 32;
    uint32_t soffB0 = soffA;
    uint32_t soffB1 = soffA + 128u * 80;
    const float* srcA  = A + (size_t)(m0 + ra_) * Dd + half * 16;
    const float* srcB0 = B + (size_t)(n0 + ra_) * Dd + half * 16;
    const float* srcB1 = B + (size_t)(n0 + 128 + ra_) * Dd + half * 16;

    FragC acc[4][4];
#pragma unroll
    for (int mi = 0; mi < 4; ++mi)
#pragma unroll
        for (int pj = 0; pj < 4; ++pj)
            wmma::fill_fragment(acc[mi][pj], 0.f);

    float ra[16], rb0[16], rb1[16];
    load16(ra, srcA); load16(rb0, srcB0); load16(rb1, srcB1);
    store_regs(sm, ra, rb0, rb1, soffA, soffB0, soffB1);
    __syncthreads();

    const int NK = Dd / 32;
    for (int kc = 0; kc < NK; ++kc) {
        char* buf = sm + (size_t)(kc & 1) * BUF_B;
        bool pre = (kc + 1 < NK);
        if (pre) {
            int c = (kc + 1) * 32;
            load16(ra, srcA + c); load16(rb0, srcB0 + c); load16(rb1, srcB1 + c);
        }
        mma_chunk64(buf, wm, wn, acc);
        if (pre) {
            char* nb = sm + (size_t)((kc + 1) & 1) * BUF_B;
            store_regs(nb, ra, rb0, rb1, soffA, soffB0, soffB1);
        }
        __syncthreads();
    }

    store_stage(stage, wm, wn, acc);
    __syncthreads();

    int r = tid >> 1;
    int c0 = (tid & 1) * 128;
    const float* sr = stage + (size_t)r * STG_P + c0;
    float* cr = C + (size_t)(m0 + r) * Dd + n0 + c0;
#pragma unroll
    for (int j = 0; j < 32; ++j)
        ((float4*)cr)[j] = ((const float4*)sr)[j];
}

// ---------------------------------------------------------------------------
// wmma flash: scores = y . x^T + bt ; softmax ; rank-1 w.  (256 threads)
// q-block 128, t-block 256. grid (Ss/128, Bb). Same pipeline order.
// ---------------------------------------------------------------------------
__global__ void __launch_bounds__(256, 1)
wmma_flash(const float* __restrict__ x, const float* __restrict__ bo,
           float* __restrict__ out)
{
    extern __shared__ char sm[];
    int tid = threadIdx.x;
    int wid = tid >> 5;
    int wm = wid & 1, wn = wid >> 1;
    int b = blockIdx.y;
    int q0 = blockIdx.x * 128;

    float* stage = (float*)sm;
    float* ws  = (float*)(sm + FL_WS);
    float* bts = (float*)(sm + FL_BT);

    const float* qb = g_y + ((size_t)b * Ss + q0) * Dd;
    const float* kb = x + (size_t)b * Ss * Dd;
    const float bo0 = __ldg(bo);

    int ra_ = tid >> 1;
    int half = tid & 1;
    uint32_t soffA  = (uint32_t)ra_ * 80 + half * 32;
    uint32_t soffB1 = soffA + 128u * 80;
    const float* srcA = qb + (size_t)ra_ * Dd + half * 16;

    const int NK = Dd / 32;
    float rm = -1e30f, rl = 0.f, rc = 0.f;   // row = tid>>1, replicated in pair

    for (int t0 = 0; t0 < Ss; t0 += 256) {
        const float* srcB0 = kb + (size_t)(t0 + ra_) * Dd + half * 16;
        const float* srcB1 = kb + (size_t)(t0 + 128 + ra_) * Dd + half * 16;
        ws[tid]  = g_w[(size_t)b * Ss + t0 + tid];
        bts[tid] = g_bt[(size_t)b * Ss + t0 + tid];

        FragC acc[4][4];
#pragma unroll
        for (int mi = 0; mi < 4; ++mi)
#pragma unroll
            for (int pj = 0; pj < 4; ++pj)
                wmma::fill_fragment(acc[mi][pj], 0.f);

        float ra[16], rb0[16], rb1[16];
        load16(ra, srcA); load16(rb0, srcB0); load16(rb1, srcB1);
        store_regs(sm, ra, rb0, rb1, soffA, soffA, soffB1);
        __syncthreads();

        for (int kc = 0; kc < NK; ++kc) {
            char* buf = sm + (size_t)(kc & 1) * BUF_B;
            bool pre = (kc + 1 < NK);
            if (pre) {
                int c = (kc + 1) * 32;
                load16(ra, srcA + c); load16(rb0, srcB0 + c); load16(rb1, srcB1 + c);
            }
            mma_chunk64(buf, wm, wn, acc);
            if (pre) {
                char* nb = sm + (size_t)((kc + 1) & 1) * BUF_B;
                store_regs(nb, ra, rb0, rb1, soffA, soffA, soffB1);
            }
            __syncthreads();
        }

        store_stage(stage, wm, wn, acc);
        __syncthreads();

        // pair softmax: thread handles row=tid>>1, cols [half*128, +128)
        {
            int row = tid >> 1;
            const float4* rp = (const float4*)(stage + (size_t)row * STG_P + half * 128);
            const float4* btp = (const float4*)(bts + half * 128);
            float m = -1e30f;
#pragma unroll 8
            for (int j = 0; j < 32; ++j) {
                float4 s4 = rp[j];
                float4 b4 = btp[j];
                s4.x += b4.x; s4.y += b4.y; s4.z += b4.z; s4.w += b4.w;
                m = fmaxf(m, fmaxf(fmaxf(s4.x, s4.y), fmaxf(s4.z, s4.w)));
            }
            m = fmaxf(m, __shfl_xor_sync(0xffffffffu, m, 1));
            float nm = fmaxf(rm, m);
            float f = __expf(rm - nm);
            float tl = 0.f, ta = 0.f;
            const float4* wp = (const float4*)(ws + half * 128);
#pragma unroll 8
            for (int j = 0; j < 32; ++j) {
                float4 s4 = rp[j];
                float4 b4 = btp[j];
                float4 w4 = wp[j];
                float p0 = __expf(s4.x + b4.x - nm);
                float p1 = __expf(s4.y + b4.y - nm);
                float p2 = __expf(s4.z + b4.z - nm);
                float p3 = __expf(s4.w + b4.w - nm);
                tl += (p0 + p1) + (p2 + p3);
                ta += p0 * w4.x + p1 * w4.y + p2 * w4.z + p3 * w4.w;
            }
            tl += __shfl_xor_sync(0xffffffffu, tl, 1);
            ta += __shfl_xor_sync(0xffffffffu, ta, 1);
            rl = rl * f + tl;
            rc = rc * f + ta;
            rm = nm;
        }
        __syncthreads();
    }

    if ((tid & 1) == 0)
        out[(size_t)b * Ss + q0 + (tid >> 1)] = rc / rl + bo0;
}

// ---------------------------------------------------------------------------
extern "C" void kernel_launch(void* const* d_in, const int* in_sizes, int n_in,
                              void* d_out, int out_size)
{
    const float* x  = (const float*)d_in[0];
    const float* Wq = (const float*)d_in[1];
    const float* bq = (const float*)d_in[2];
    const float* Wk = (const float*)d_in[3];
    const float* bk = (const float*)d_in[4];
    const float* Wv = (const float*)d_in[5];
    const float* bv = (const float*)d_in[6];
    const float* Wo = (const float*)d_in[7];
    const float* bo = (const float*)d_in[8];
    float* out = (float*)d_out;
    (void)bk; (void)in_sizes; (void)n_in; (void)out_size;

    static bool attr_done = false;
    if (!attr_done) {
        cudaFuncSetAttribute(wmma_abt,
                             cudaFuncAttributeMaxDynamicSharedMemorySize, ABT_SMEM);
        cudaFuncSetAttribute(wmma_flash,
                             cudaFuncAttributeMaxDynamicSharedMemorySize, FLASH_SMEM);
        attr_done = true;
    }

    float* yq = nullptr; cudaGetSymbolAddress((void**)&yq, g_y);
    float* mt = nullptr; cudaGetSymbolAddress((void**)&mt, g_mt);
    float* uu = nullptr; cudaGetSymbolAddress((void**)&uu, g_u);
    float* hh = nullptr; cudaGetSymbolAddress((void**)&hh, g_h);

    // scalars + per-feature vectors
    prep_c<<<1, 256>>>(bv, Wo);
    gemv_row<<<Dd, 256>>>(Wv, Wo, uu);    // u = Wv @ Wo
    gemv_row<<<Dd, 256>>>(Wk, bq, hh);    // h = Wk @ bq
    gemv_row2<<<Mtot, 256>>>(x);          // w = x.u + c ; bt = x.h

    // Mt = Wk @ Wq^T, then y = x @ Mt^T
    {
        dim3 gm(Dd / 256, Dd / 128);
        wmma_abt<<<gm, 256, ABT_SMEM>>>(Wk, Wq, mt);
        dim3 gy(Dd / 256, Mtot / 128);
        wmma_abt<<<gy, 256, ABT_SMEM>>>(x, mt, yq);
    }

    // fused scores(y.x^T + bt) + softmax + rank-1 w reduction
    dim3 gf(Ss / 128, Bb);
    wmma_flash<<<gf, 256, FLASH_SMEM>>>(x, bo, out);
}

// round 11
// speedup vs baseline: 1.1602x; 1.0590x over previous
#include <cuda_runtime.h>
#include <cuda_bf16.h>
#include <mma.h>
#include <cstdint>

using namespace nvcuda;

#define Bb 8
#define Ss 2048
#define Dd 1024
#define Mtot (Bb * Ss)
#define NSPLIT 8                      // t-splits (Ss / 256)

// ---------------------------------------------------------------------------
// Device-global scratch
// ---------------------------------------------------------------------------
__device__ float g_y[(size_t)Mtot * Dd];   // y = x @ Mt^T
__device__ float g_mt[(size_t)Dd * Dd];    // Mt = Wk @ Wq^T
__device__ float g_w[Mtot];                // v_t . Wo per token
__device__ float g_bt[Mtot];               // x_t . (Wk bq)
__device__ float g_u[Dd];                  // Wv @ Wo
__device__ float g_h[Dd];                  // Wk @ bq
__device__ float g_c;                      // bv . Wo
__device__ float g_pm[(size_t)Mtot * NSPLIT];  // partial max
__device__ float g_pl[(size_t)Mtot * NSPLIT];  // partial sum exp
__device__ float g_pa[(size_t)Mtot * NSPLIT];  // partial sum exp*w

// ---------------------------------------------------------------------------
// prep kernels (validated)
// ---------------------------------------------------------------------------
__global__ void prep_c(const float* __restrict__ bv, const float* __restrict__ Wo)
{
    __shared__ float red[8];
    int tid = threadIdx.x;
    float4 a = ((const float4*)bv)[tid];
    float4 b = ((const float4*)Wo)[tid];
    float s = a.x * b.x + a.y * b.y + a.z * b.z + a.w * b.w;
    #pragma unroll
    for (int off = 16; off; off >>= 1) s += __shfl_xor_sync(0xffffffffu, s, off);
    if ((tid & 31) == 0) red[tid >> 5] = s;
    __syncthreads();
    if (tid < 8) {
        s = red[tid];
        #pragma unroll
        for (int off = 4; off; off >>= 1) s += __shfl_xor_sync(0xffu, s, off);
        if (tid == 0) g_c = s;
    }
}

__global__ void gemv_row(const float* __restrict__ A, const float* __restrict__ vec,
                         float* __restrict__ outv)
{
    __shared__ float red[8];
    int m = blockIdx.x;
    int tid = threadIdx.x;
    float4 a = ((const float4*)(A + (size_t)m * Dd))[tid];
    float4 u = ((const float4*)vec)[tid];
    float s = a.x * u.x + a.y * u.y + a.z * u.z + a.w * u.w;
    #pragma unroll
    for (int off = 16; off; off >>= 1) s += __shfl_xor_sync(0xffffffffu, s, off);
    if ((tid & 31) == 0) red[tid >> 5] = s;
    __syncthreads();
    if (tid < 8) {
        s = red[tid];
        #pragma unroll
        for (int off = 4; off; off >>= 1) s += __shfl_xor_sync(0xffu, s, off);
        if (tid == 0) outv[m] = s;
    }
}

__global__ void gemv_row2(const float* __restrict__ x)
{
    __shared__ float red1[8], red2[8];
    int m = blockIdx.x;
    int tid = threadIdx.x;
    float4 a = ((const float4*)(x + (size_t)m * Dd))[tid];
    float4 u = ((const float4*)g_u)[tid];
    float4 h = ((const float4*)g_h)[tid];
    float s1 = a.x * u.x + a.y * u.y + a.z * u.z + a.w * u.w;
    float s2 = a.x * h.x + a.y * h.y + a.z * h.z + a.w * h.w;
    #pragma unroll
    for (int off = 16; off; off >>= 1) {
        s1 += __shfl_xor_sync(0xffffffffu, s1, off);
        s2 += __shfl_xor_sync(0xffffffffu, s2, off);
    }
    if ((tid & 31) == 0) { red1[tid >> 5] = s1; red2[tid >> 5] = s2; }
    __syncthreads();
    if (tid < 8) {
        s1 = red1[tid]; s2 = red2[tid];
        #pragma unroll
        for (int off = 4; off; off >>= 1) {
            s1 += __shfl_xor_sync(0xffu, s1, off);
            s2 += __shfl_xor_sync(0xffu, s2, off);
        }
        if (tid == 0) { g_w[m] = s1 + g_c; g_bt[m] = s2; }
    }
}

// ---------------------------------------------------------------------------
// wmma machinery: CTA tile 128(m) x 256(n), 8 warps of 64x64, k-chunk 32.
// ---------------------------------------------------------------------------
#define TP_E 40
#define A_T_B (128 * 80)
#define B_T_B (256 * 80)
#define OFF_AL A_T_B
#define OFF_BH (2 * A_T_B)
#define OFF_BL (2 * A_T_B + B_T_B)
#define BUF_B  (2 * A_T_B + 2 * B_T_B) // 61440
#define STG_P  260
#define STG_B  (128 * STG_P * 4)       // 133120
#define FL_WS  STG_B
#define FL_BT  (STG_B + 1024)
#define ABT_SMEM   STG_B
#define FLASH_SMEM (STG_B + 2048)

typedef wmma::fragment<wmma::matrix_a, 16, 16, 16, __nv_bfloat16, wmma::row_major> FragA;
typedef wmma::fragment<wmma::matrix_b, 16, 16, 16, __nv_bfloat16, wmma::col_major> FragB;
typedef wmma::fragment<wmma::accumulator, 16, 16, 16, float> FragC;

__device__ __forceinline__ void load16(float* v, const float* p) {
#pragma unroll
    for (int i = 0; i < 4; ++i) ((float4*)v)[i] = ((const float4*)p)[i];
}

__device__ __forceinline__ void split16_store(char* hi, char* lo, uint32_t off,
                                              const float* v) {
    alignas(16) __nv_bfloat16 h[16], l[16];
#pragma unroll
    for (int j = 0; j < 16; ++j) {
        float f = v[j];
        __nv_bfloat16 hh = __float2bfloat16(f);
        h[j] = hh;
        l[j] = __float2bfloat16(f - __bfloat162float(hh));
    }
    *(uint4*)(hi + off)      = ((const uint4*)h)[0];
    *(uint4*)(hi + off + 16) = ((const uint4*)h)[1];
    *(uint4*)(lo + off)      = ((const uint4*)l)[0];
    *(uint4*)(lo + off + 16) = ((const uint4*)l)[1];
}

__device__ __forceinline__ void store_regs(char* buf, const float* ra,
                                           const float* rb0, const float* rb1,
                                           uint32_t soffA, uint32_t soffB0,
                                           uint32_t soffB1)
{
    split16_store(buf, buf + OFF_AL, soffA, ra);
    split16_store(buf + OFF_BH, buf + OFF_BL, soffB0, rb0);
    split16_store(buf + OFF_BH, buf + OFF_BL, soffB1, rb1);
}

__device__ __forceinline__ void mma_chunk64(const char* buf, int wm, int wn,
                                            FragC (&acc)[4][4])
{
    const __nv_bfloat16* tA  = (const __nv_bfloat16*)(buf);
    const __nv_bfloat16* tAl = (const __nv_bfloat16*)(buf + OFF_AL);
    const __nv_bfloat16* tB  = (const __nv_bfloat16*)(buf + OFF_BH);
    const __nv_bfloat16* tBl = (const __nv_bfloat16*)(buf + OFF_BL);
#pragma unroll
    for (int ks = 0; ks < 2; ++ks) {
        FragA ah[4], al[4];
#pragma unroll
        for (int mi = 0; mi < 4; ++mi) {
            int ro = (64 * wm + 16 * mi) * TP_E + ks * 16;
            wmma::load_matrix_sync(ah[mi], tA + ro, TP_E);
            wmma::load_matrix_sync(al[mi], tAl + ro, TP_E);
        }
#pragma unroll
        for (int pj = 0; pj < 4; ++pj) {
            int ro = (64 * wn + 16 * pj) * TP_E + ks * 16;
            FragB bh, bl;
            wmma::load_matrix_sync(bh, tB + ro, TP_E);
            wmma::load_matrix_sync(bl, tBl + ro, TP_E);
#pragma unroll
            for (int mi = 0; mi < 4; ++mi) {
                wmma::mma_sync(acc[mi][pj], ah[mi], bh, acc[mi][pj]);
                wmma::mma_sync(acc[mi][pj], ah[mi], bl, acc[mi][pj]);
                wmma::mma_sync(acc[mi][pj], al[mi], bh, acc[mi][pj]);
            }
        }
    }
}

__device__ __forceinline__ void store_stage(float* stage, int wm, int wn,
                                            FragC (&acc)[4][4])
{
#pragma unroll
    for (int mi = 0; mi < 4; ++mi)
#pragma unroll
        for (int pj = 0; pj < 4; ++pj)
            wmma::store_matrix_sync(
                stage + (size_t)(64 * wm + 16 * mi) * STG_P + 64 * wn + 16 * pj,
                acc[mi][pj], STG_P, wmma::mem_row_major);
}

// ---------------------------------------------------------------------------
// wmma A@B^T: C[m0+128, n0+256] = A[m0..,:] . B[n0..,:]^T   (validated R10)
// ---------------------------------------------------------------------------
__global__ void __launch_bounds__(256, 1)
wmma_abt(const float* __restrict__ A, const float* __restrict__ B,
         float* __restrict__ C)
{
    extern __shared__ char sm[];
    int tid = threadIdx.x;
    int wid = tid >> 5;
    int wm = wid & 1, wn = wid >> 1;
    int m0 = blockIdx.y * 128;
    int n0 = blockIdx.x * 256;

    float* stage = (float*)sm;

    int ra_ = tid >> 1;
    int half = tid & 1;
    uint32_t soffA  = (uint32_t)ra_ * 80 + half * 32;
    uint32_t soffB0 = soffA;
    uint32_t soffB1 = soffA + 128u * 80;
    const float* srcA  = A + (size_t)(m0 + ra_) * Dd + half * 16;
    const float* srcB0 = B + (size_t)(n0 + ra_) * Dd + half * 16;
    const float* srcB1 = B + (size_t)(n0 + 128 + ra_) * Dd + half * 16;

    FragC acc[4][4];
#pragma unroll
    for (int mi = 0; mi < 4; ++mi)
#pragma unroll
        for (int pj = 0; pj < 4; ++pj)
            wmma::fill_fragment(acc[mi][pj], 0.f);

    float ra[16], rb0[16], rb1[16];
    load16(ra, srcA); load16(rb0, srcB0); load16(rb1, srcB1);
    store_regs(sm, ra, rb0, rb1, soffA, soffB0, soffB1);
    __syncthreads();

    const int NK = Dd / 32;
    for (int kc = 0; kc < NK; ++kc) {
        char* buf = sm + (size_t)(kc & 1) * BUF_B;
        bool pre = (kc + 1 < NK);
        if (pre) {
            int c = (kc + 1) * 32;
            load16(ra, srcA + c); load16(rb0, srcB0 + c); load16(rb1, srcB1 + c);
        }
        mma_chunk64(buf, wm, wn, acc);
        if (pre) {
            char* nb = sm + (size_t)((kc + 1) & 1) * BUF_B;
            store_regs(nb, ra, rb0, rb1, soffA, soffB0, soffB1);
        }
        __syncthreads();
    }

    store_stage(stage, wm, wn, acc);
    __syncthreads();

    int r = tid >> 1;
    int c0 = (tid & 1) * 128;
    const float* sr = stage + (size_t)r * STG_P + c0;
    float* cr = C + (size_t)(m0 + r) * Dd + n0 + c0;
#pragma unroll
    for (int j = 0; j < 32; ++j)
        ((float4*)cr)[j] = ((const float4*)sr)[j];
}

// ---------------------------------------------------------------------------
// wmma flash, t-split: one CTA = one 128q x 256t score tile; one-shot softmax
// partial (m, l, sum p*w) -> global. grid (Ss/128, Bb, NSPLIT), 256 threads.
// ---------------------------------------------------------------------------
__global__ void __launch_bounds__(256, 1)
wmma_flash(const float* __restrict__ x)
{
    extern __shared__ char sm[];
    int tid = threadIdx.x;
    int wid = tid >> 5;
    int wm = wid & 1, wn = wid >> 1;
    int b = blockIdx.y;
    int q0 = blockIdx.x * 128;
    int split = blockIdx.z;
    int t0 = split * 256;

    float* stage = (float*)sm;
    float* ws  = (float*)(sm + FL_WS);
    float* bts = (float*)(sm + FL_BT);

    const float* qb = g_y + ((size_t)b * Ss + q0) * Dd;
    const float* kb = x + (size_t)b * Ss * Dd;

    int ra_ = tid >> 1;
    int half = tid & 1;
    uint32_t soffA  = (uint32_t)ra_ * 80 + half * 32;
    uint32_t soffB1 = soffA + 128u * 80;
    const float* srcA  = qb + (size_t)ra_ * Dd + half * 16;
    const float* srcB0 = kb + (size_t)(t0 + ra_) * Dd + half * 16;
    const float* srcB1 = kb + (size_t)(t0 + 128 + ra_) * Dd + half * 16;

    ws[tid]  = g_w[(size_t)b * Ss + t0 + tid];
    bts[tid] = g_bt[(size_t)b * Ss + t0 + tid];

    FragC acc[4][4];
#pragma unroll
    for (int mi = 0; mi < 4; ++mi)
#pragma unroll
        for (int pj = 0; pj < 4; ++pj)
            wmma::fill_fragment(acc[mi][pj], 0.f);

    float ra[16], rb0[16], rb1[16];
    load16(ra, srcA); load16(rb0, srcB0); load16(rb1, srcB1);
    store_regs(sm, ra, rb0, rb1, soffA, soffA, soffB1);
    __syncthreads();

    const int NK = Dd / 32;
    for (int kc = 0; kc < NK; ++kc) {
        char* buf = sm + (size_t)(kc & 1) * BUF_B;
        bool pre = (kc + 1 < NK);
        if (pre) {
            int c = (kc + 1) * 32;
            load16(ra, srcA + c); load16(rb0, srcB0 + c); load16(rb1, srcB1 + c);
        }
        mma_chunk64(buf, wm, wn, acc);
        if (pre) {
            char* nb = sm + (size_t)((kc + 1) & 1) * BUF_B;
            store_regs(nb, ra, rb0, rb1, soffA, soffA, soffB1);
        }
        __syncthreads();
    }

    store_stage(stage, wm, wn, acc);
    __syncthreads();

    // one-shot softmax partial: 2 threads per row, each 128 cols
    {
        int row = tid >> 1;
        const float4* rp = (const float4*)(stage + (size_t)row * STG_P + half * 128);
        const float4* btp = (const float4*)(bts + half * 128);
        float m = -1e30f;
#pragma unroll 8
        for (int j = 0; j < 32; ++j) {
            float4 s4 = rp[j];
            float4 b4 = btp[j];
            s4.x += b4.x; s4.y += b4.y; s4.z += b4.z; s4.w += b4.w;
            m = fmaxf(m, fmaxf(fmaxf(s4.x, s4.y), fmaxf(s4.z, s4.w)));
        }
        m = fmaxf(m, __shfl_xor_sync(0xffffffffu, m, 1));
        float tl = 0.f, ta = 0.f;
        const float4* wp = (const float4*)(ws + half * 128);
#pragma unroll 8
        for (int j = 0; j < 32; ++j) {
            float4 s4 = rp[j];
            float4 b4 = btp[j];
            float4 w4 = wp[j];
            float p0 = __expf(s4.x + b4.x - m);
            float p1 = __expf(s4.y + b4.y - m);
            float p2 = __expf(s4.z + b4.z - m);
            float p3 = __expf(s4.w + b4.w - m);
            tl += (p0 + p1) + (p2 + p3);
            ta += p0 * w4.x + p1 * w4.y + p2 * w4.z + p3 * w4.w;
        }
        tl += __shfl_xor_sync(0xffffffffu, tl, 1);
        ta += __shfl_xor_sync(0xffffffffu, ta, 1);
        if (half == 0) {
            size_t idx = ((size_t)b * Ss + q0 + row) * NSPLIT + split;
            g_pm[idx] = m;
            g_pl[idx] = tl;
            g_pa[idx] = ta;
        }
    }
}

// ---------------------------------------------------------------------------
// combine partials: out[r] = (sum_a a_i e^{m_i-M}) / (sum_l l_i e^{m_i-M}) + bo
// ---------------------------------------------------------------------------
__global__ void combine_partials(const float* __restrict__ bo,
                                 float* __restrict__ out)
{
    int r = blockIdx.x * 256 + threadIdx.x;
    const float* pm = g_pm + (size_t)r * NSPLIT;
    const float* pl = g_pl + (size_t)r * NSPLIT;
    const float* pa = g_pa + (size_t)r * NSPLIT;
    float M = -1e30f;
#pragma unroll
    for (int i = 0; i < NSPLIT; ++i) M = fmaxf(M, pm[i]);
    float L = 0.f, A = 0.f;
#pragma unroll
    for (int i = 0; i < NSPLIT; ++i) {
        float f = __expf(pm[i] - M);
        L += pl[i] * f;
        A += pa[i] * f;
    }
    out[r] = A / L + bo[0];
}

// ---------------------------------------------------------------------------
extern "C" void kernel_launch(void* const* d_in, const int* in_sizes, int n_in,
                              void* d_out, int out_size)
{
    const float* x  = (const float*)d_in[0];
    const float* Wq = (const float*)d_in[1];
    const float* bq = (const float*)d_in[2];
    const float* Wk = (const float*)d_in[3];
    const float* bk = (const float*)d_in[4];
    const float* Wv = (const float*)d_in[5];
    const float* bv = (const float*)d_in[6];
    const float* Wo = (const float*)d_in[7];
    const float* bo = (const float*)d_in[8];
    float* out = (float*)d_out;
    (void)bk; (void)in_sizes; (void)n_in; (void)out_size;

    static bool attr_done = false;
    if (!attr_done) {
        cudaFuncSetAttribute(wmma_abt,
                             cudaFuncAttributeMaxDynamicSharedMemorySize, ABT_SMEM);
        cudaFuncSetAttribute(wmma_flash,
                             cudaFuncAttributeMaxDynamicSharedMemorySize, FLASH_SMEM);
        attr_done = true;
    }

    float* yq = nullptr; cudaGetSymbolAddress((void**)&yq, g_y);
    float* mt = nullptr; cudaGetSymbolAddress((void**)&mt, g_mt);
    float* uu = nullptr; cudaGetSymbolAddress((void**)&uu, g_u);
    float* hh = nullptr; cudaGetSymbolAddress((void**)&hh, g_h);

    // scalars + per-feature vectors
    prep_c<<<1, 256>>>(bv, Wo);
    gemv_row<<<Dd, 256>>>(Wv, Wo, uu);    // u = Wv @ Wo
    gemv_row<<<Dd, 256>>>(Wk, bq, hh);    // h = Wk @ bq
    gemv_row2<<<Mtot, 256>>>(x);          // w = x.u + c ; bt = x.h

    // Mt = Wk @ Wq^T, then y = x @ Mt^T
    {
        dim3 gm(Dd / 256, Dd / 128);
        wmma_abt<<<gm, 256, ABT_SMEM>>>(Wk, Wq, mt);
        dim3 gy(Dd / 256, Mtot / 128);
        wmma_abt<<<gy, 256, ABT_SMEM>>>(x, mt, yq);
    }

    // t-split flash partials + combine
    dim3 gf(Ss / 128, Bb, NSPLIT);
    wmma_flash<<<gf, 256, FLASH_SMEM>>>(x);
    combine_partials<<<Mtot / 256, 256>>>(bo, out);
}

// round 12
// speedup vs baseline: 1.2691x; 1.0939x over previous
#include <cuda_runtime.h>
#include <cuda_bf16.h>
#include <mma.h>
#include <cstdint>

using namespace nvcuda;

#define Bb 8
#define Ss 2048
#define Dd 1024
#define Mtot (Bb * Ss)
#define NSPLIT 8

// ---------------------------------------------------------------------------
// Device-global scratch (all operands pre-split bf16 hi/lo)
// ---------------------------------------------------------------------------
__device__ __nv_bfloat16 g_xhi[(size_t)Mtot * Dd];
__device__ __nv_bfloat16 g_xlo[(size_t)Mtot * Dd];
__device__ __nv_bfloat16 g_yhi[(size_t)Mtot * Dd];
__device__ __nv_bfloat16 g_ylo[(size_t)Mtot * Dd];
__device__ __nv_bfloat16 g_wkhi[(size_t)Dd * Dd];
__device__ __nv_bfloat16 g_wklo[(size_t)Dd * Dd];
__device__ __nv_bfloat16 g_wqhi[(size_t)Dd * Dd];
__device__ __nv_bfloat16 g_wqlo[(size_t)Dd * Dd];
__device__ __nv_bfloat16 g_mthi[(size_t)Dd * Dd];
__device__ __nv_bfloat16 g_mtlo[(size_t)Dd * Dd];
__device__ float g_w[Mtot];
__device__ float g_bt[Mtot];
__device__ float g_u[Dd];
__device__ float g_h[Dd];
__device__ float g_c;
__device__ float g_pm[(size_t)Mtot * NSPLIT];
__device__ float g_pl[(size_t)Mtot * NSPLIT];
__device__ float g_pa[(size_t)Mtot * NSPLIT];

// ---------------------------------------------------------------------------
// split2: fp32 -> bf16 hi/lo (elementwise, 8 per thread)
// ---------------------------------------------------------------------------
__global__ void split2(const float* __restrict__ in,
                       __nv_bfloat16* __restrict__ hi,
                       __nv_bfloat16* __restrict__ lo)
{
    size_t i0 = ((size_t)blockIdx.x * 256 + threadIdx.x) * 8;
    float4 a = *(const float4*)(in + i0);
    float4 b = *(const float4*)(in + i0 + 4);
    float v[8] = {a.x, a.y, a.z, a.w, b.x, b.y, b.z, b.w};
    alignas(16) __nv_bfloat16 h[8], l[8];
#pragma unroll
    for (int j = 0; j < 8; ++j) {
        __nv_bfloat16 hh = __float2bfloat16(v[j]);
        h[j] = hh;
        l[j] = __float2bfloat16(v[j] - __bfloat162float(hh));
    }
    *(uint4*)(hi + i0) = *(uint4*)h;
    *(uint4*)(lo + i0) = *(uint4*)l;
}

// ---------------------------------------------------------------------------
// prep kernels (validated)
// ---------------------------------------------------------------------------
__global__ void prep_c(const float* __restrict__ bv, const float* __restrict__ Wo)
{
    __shared__ float red[8];
    int tid = threadIdx.x;
    float4 a = ((const float4*)bv)[tid];
    float4 b = ((const float4*)Wo)[tid];
    float s = a.x * b.x + a.y * b.y + a.z * b.z + a.w * b.w;
    #pragma unroll
    for (int off = 16; off; off >>= 1) s += __shfl_xor_sync(0xffffffffu, s, off);
    if ((tid & 31) == 0) red[tid >> 5] = s;
    __syncthreads();
    if (tid < 8) {
        s = red[tid];
        #pragma unroll
        for (int off = 4; off; off >>= 1) s += __shfl_xor_sync(0xffu, s, off);
        if (tid == 0) g_c = s;
    }
}

__global__ void gemv_row(const float* __restrict__ A, const float* __restrict__ vec,
                         float* __restrict__ outv)
{
    __shared__ float red[8];
    int m = blockIdx.x;
    int tid = threadIdx.x;
    float4 a = ((const float4*)(A + (size_t)m * Dd))[tid];
    float4 u = ((const float4*)vec)[tid];
    float s = a.x * u.x + a.y * u.y + a.z * u.z + a.w * u.w;
    #pragma unroll
    for (int off = 16; off; off >>= 1) s += __shfl_xor_sync(0xffffffffu, s, off);
    if ((tid & 31) == 0) red[tid >> 5] = s;
    __syncthreads();
    if (tid < 8) {
        s = red[tid];
        #pragma unroll
        for (int off = 4; off; off >>= 1) s += __shfl_xor_sync(0xffu, s, off);
        if (tid == 0) outv[m] = s;
    }
}

__global__ void gemv_row2(const float* __restrict__ x)
{
    __shared__ float red1[8], red2[8];
    int m = blockIdx.x;
    int tid = threadIdx.x;
    float4 a = ((const float4*)(x + (size_t)m * Dd))[tid];
    float4 u = ((const float4*)g_u)[tid];
    float4 h = ((const float4*)g_h)[tid];
    float s1 = a.x * u.x + a.y * u.y + a.z * u.z + a.w * u.w;
    float s2 = a.x * h.x + a.y * h.y + a.z * h.z + a.w * h.w;
    #pragma unroll
    for (int off = 16; off; off >>= 1) {
        s1 += __shfl_xor_sync(0xffffffffu, s1, off);
        s2 += __shfl_xor_sync(0xffffffffu, s2, off);
    }
    if ((tid & 31) == 0) { red1[tid >> 5] = s1; red2[tid >> 5] = s2; }
    __syncthreads();
    if (tid < 8) {
        s1 = red1[tid]; s2 = red2[tid];
        #pragma unroll
        for (int off = 4; off; off >>= 1) {
            s1 += __shfl_xor_sync(0xffu, s1, off);
            s2 += __shfl_xor_sync(0xffu, s2, off);
        }
        if (tid == 0) { g_w[m] = s1 + g_c; g_bt[m] = s2; }
    }
}

// ---------------------------------------------------------------------------
// wmma machinery: CTA tile 128(m) x 256(n), 8 warps of 64x64, k-chunk 32.
// smem layout identical to validated R10/R11.
// ---------------------------------------------------------------------------
#define TP_E 40
#define A_T_B (128 * 80)
#define B_T_B (256 * 80)
#define OFF_AL A_T_B
#define OFF_BH (2 * A_T_B)
#define OFF_BL (2 * A_T_B + B_T_B)
#define BUF_B  (2 * A_T_B + 2 * B_T_B)
#define STG_P  260
#define STG_B  (128 * STG_P * 4)
#define FL_WS  STG_B
#define FL_BT  (STG_B + 1024)
#define ABT_SMEM   STG_B
#define FLASH_SMEM (STG_B + 2048)

typedef wmma::fragment<wmma::matrix_a, 16, 16, 16, __nv_bfloat16, wmma::row_major> FragA;
typedef wmma::fragment<wmma::matrix_b, 16, 16, 16, __nv_bfloat16, wmma::col_major> FragB;
typedef wmma::fragment<wmma::accumulator, 16, 16, 16, float> FragC;

// Per-thread prefetch: 16 bf16 (32B = 2 uint4) from each of 6 sources.
struct Pref { uint4 r[12]; };

__device__ __forceinline__ void ldg_chunk(Pref& p,
    const __nv_bfloat16* sAh, const __nv_bfloat16* sAl,
    const __nv_bfloat16* sB0h, const __nv_bfloat16* sB0l,
    const __nv_bfloat16* sB1h, const __nv_bfloat16* sB1l, int col)
{
    p.r[0]  = ((const uint4*)(sAh  + col))[0]; p.r[1]  = ((const uint4*)(sAh  + col))[1];
    p.r[2]  = ((const uint4*)(sAl  + col))[0]; p.r[3]  = ((const uint4*)(sAl  + col))[1];
    p.r[4]  = ((const uint4*)(sB0h + col))[0]; p.r[5]  = ((const uint4*)(sB0h + col))[1];
    p.r[6]  = ((const uint4*)(sB0l + col))[0]; p.r[7]  = ((const uint4*)(sB0l + col))[1];
    p.r[8]  = ((const uint4*)(sB1h + col))[0]; p.r[9]  = ((const uint4*)(sB1h + col))[1];
    p.r[10] = ((const uint4*)(sB1l + col))[0]; p.r[11] = ((const uint4*)(sB1l + col))[1];
}

__device__ __forceinline__ void sts_chunk(char* buf, const Pref& p,
                                          uint32_t soffA, uint32_t soffB0,
                                          uint32_t soffB1)
{
    *(uint4*)(buf + soffA)                 = p.r[0];
    *(uint4*)(buf + soffA + 16)            = p.r[1];
    *(uint4*)(buf + OFF_AL + soffA)        = p.r[2];
    *(uint4*)(buf + OFF_AL + soffA + 16)   = p.r[3];
    *(uint4*)(buf + OFF_BH + soffB0)       = p.r[4];
    *(uint4*)(buf + OFF_BH + soffB0 + 16)  = p.r[5];
    *(uint4*)(buf + OFF_BL + soffB0)       = p.r[6];
    *(uint4*)(buf + OFF_BL + soffB0 + 16)  = p.r[7];
    *(uint4*)(buf + OFF_BH + soffB1)       = p.r[8];
    *(uint4*)(buf + OFF_BH + soffB1 + 16)  = p.r[9];
    *(uint4*)(buf + OFF_BL + soffB1)       = p.r[10];
    *(uint4*)(buf + OFF_BL + soffB1 + 16)  = p.r[11];
}

__device__ __forceinline__ void mma_chunk64(const char* buf, int wm, int wn,
                                            FragC (&acc)[4][4])
{
    const __nv_bfloat16* tA  = (const __nv_bfloat16*)(buf);
    const __nv_bfloat16* tAl = (const __nv_bfloat16*)(buf + OFF_AL);
    const __nv_bfloat16* tB  = (const __nv_bfloat16*)(buf + OFF_BH);
    const __nv_bfloat16* tBl = (const __nv_bfloat16*)(buf + OFF_BL);
#pragma unroll
    for (int ks = 0; ks < 2; ++ks) {
        FragA ah[4], al[4];
#pragma unroll
        for (int mi = 0; mi < 4; ++mi) {
            int ro = (64 * wm + 16 * mi) * TP_E + ks * 16;
            wmma::load_matrix_sync(ah[mi], tA + ro, TP_E);
            wmma::load_matrix_sync(al[mi], tAl + ro, TP_E);
        }
#pragma unroll
        for (int pj = 0; pj < 4; ++pj) {
            int ro = (64 * wn + 16 * pj) * TP_E + ks * 16;
            FragB bh, bl;
            wmma::load_matrix_sync(bh, tB + ro, TP_E);
            wmma::load_matrix_sync(bl, tBl + ro, TP_E);
#pragma unroll
            for (int mi = 0; mi < 4; ++mi) {
                wmma::mma_sync(acc[mi][pj], ah[mi], bh, acc[mi][pj]);
                wmma::mma_sync(acc[mi][pj], ah[mi], bl, acc[mi][pj]);
                wmma::mma_sync(acc[mi][pj], al[mi], bh, acc[mi][pj]);
            }
        }
    }
}

__device__ __forceinline__ void store_stage(float* stage, int wm, int wn,
                                            FragC (&acc)[4][4])
{
#pragma unroll
    for (int mi = 0; mi < 4; ++mi)
#pragma unroll
        for (int pj = 0; pj < 4; ++pj)
            wmma::store_matrix_sync(
                stage + (size_t)(64 * wm + 16 * mi) * STG_P + 64 * wn + 16 * pj,
                acc[mi][pj], STG_P, wmma::mem_row_major);
}

// ---------------------------------------------------------------------------
// bf16 A@B^T with hi/lo inputs and hi/lo outputs.
// C[m0+128, n0+256]: Chi/Clo = split(A . B^T)
// ---------------------------------------------------------------------------
__global__ void __launch_bounds__(256, 1)
wmma_abt_bf(const __nv_bfloat16* __restrict__ Ahi, const __nv_bfloat16* __restrict__ Alo,
            const __nv_bfloat16* __restrict__ Bhi, const __nv_bfloat16* __restrict__ Blo,
            __nv_bfloat16* __restrict__ Chi, __nv_bfloat16* __restrict__ Clo)
{
    extern __shared__ char sm[];
    int tid = threadIdx.x;
    int wid = tid >> 5;
    int wm = wid & 1, wn = wid >> 1;
    int m0 = blockIdx.y * 128;
    int n0 = blockIdx.x * 256;

    float* stage = (float*)sm;

    int ra_ = tid >> 1;
    int half = tid & 1;
    uint32_t soffA  = (uint32_t)ra_ * 80 + half * 32;
    uint32_t soffB0 = soffA;
    uint32_t soffB1 = soffA + 128u * 80;
    size_t roA  = (size_t)(m0 + ra_) * Dd + half * 16;
    size_t roB0 = (size_t)(n0 + ra_) * Dd + half * 16;
    size_t roB1 = (size_t)(n0 + 128 + ra_) * Dd + half * 16;
    const __nv_bfloat16* sAh  = Ahi + roA;
    const __nv_bfloat16* sAl  = Alo + roA;
    const __nv_bfloat16* sB0h = Bhi + roB0;
    const __nv_bfloat16* sB0l = Blo + roB0;
    const __nv_bfloat16* sB1h = Bhi + roB1;
    const __nv_bfloat16* sB1l = Blo + roB1;

    FragC acc[4][4];
#pragma unroll
    for (int mi = 0; mi < 4; ++mi)
#pragma unroll
        for (int pj = 0; pj < 4; ++pj)
            wmma::fill_fragment(acc[mi][pj], 0.f);

    Pref p;
    ldg_chunk(p, sAh, sAl, sB0h, sB0l, sB1h, sB1l, 0);
    sts_chunk(sm, p, soffA, soffB0, soffB1);
    __syncthreads();

    const int NK = Dd / 32;
    for (int kc = 0; kc < NK; ++kc) {
        char* buf = sm + (size_t)(kc & 1) * BUF_B;
        bool pre = (kc + 1 < NK);
        if (pre) ldg_chunk(p, sAh, sAl, sB0h, sB0l, sB1h, sB1l, (kc + 1) * 32);
        mma_chunk64(buf, wm, wn, acc);
        if (pre) sts_chunk(sm + (size_t)((kc + 1) & 1) * BUF_B, p,
                           soffA, soffB0, soffB1);
        __syncthreads();
    }

    store_stage(stage, wm, wn, acc);
    __syncthreads();

    // epilogue: split fp32 stage to hi/lo bf16
    int r = tid >> 1;
    int c0 = half * 128;
    const float* sr = stage + (size_t)r * STG_P + c0;
    size_t ob = (size_t)(m0 + r) * Dd + n0 + c0;
#pragma unroll
    for (int j = 0; j < 16; ++j) {
        float4 a = ((const float4*)sr)[2 * j];
        float4 b = ((const float4*)sr)[2 * j + 1];
        float v[8] = {a.x, a.y, a.z, a.w, b.x, b.y, b.z, b.w};
        alignas(16) __nv_bfloat16 h[8], l[8];
#pragma unroll
        for (int q = 0; q < 8; ++q) {
            __nv_bfloat16 hh = __float2bfloat16(v[q]);
            h[q] = hh;
            l[q] = __float2bfloat16(v[q] - __bfloat162float(hh));
        }
        *(uint4*)(Chi + ob + j * 8) = *(uint4*)h;
        *(uint4*)(Clo + ob + j * 8) = *(uint4*)l;
    }
}

// ---------------------------------------------------------------------------
// wmma flash, t-split, bf16 pre-split inputs. grid (Ss/128, Bb, NSPLIT).
// ---------------------------------------------------------------------------
__global__ void __launch_bounds__(256, 1)
wmma_flash()
{
    extern __shared__ char sm[];
    int tid = threadIdx.x;
    int wid = tid >> 5;
    int wm = wid & 1, wn = wid >> 1;
    int b = blockIdx.y;
    int q0 = blockIdx.x * 128;
    int split = blockIdx.z;
    int t0 = split * 256;

    float* stage = (float*)sm;
    float* ws  = (float*)(sm + FL_WS);
    float* bts = (float*)(sm + FL_BT);

    int ra_ = tid >> 1;
    int half = tid & 1;
    uint32_t soffA  = (uint32_t)ra_ * 80 + half * 32;
    uint32_t soffB1 = soffA + 128u * 80;
    size_t roA  = ((size_t)b * Ss + q0 + ra_) * Dd + half * 16;
    size_t roB0 = ((size_t)b * Ss + t0 + ra_) * Dd + half * 16;
    size_t roB1 = ((size_t)b * Ss + t0 + 128 + ra_) * Dd + half * 16;
    const __nv_bfloat16* sAh  = g_yhi + roA;
    const __nv_bfloat16* sAl  = g_ylo + roA;
    const __nv_bfloat16* sB0h = g_xhi + roB0;
    const __nv_bfloat16* sB0l = g_xlo + roB0;
    const __nv_bfloat16* sB1h = g_xhi + roB1;
    const __nv_bfloat16* sB1l = g_xlo + roB1;

    ws[tid]  = g_w[(size_t)b * Ss + t0 + tid];
    bts[tid] = g_bt[(size_t)b * Ss + t0 + tid];

    FragC acc[4][4];
#pragma unroll
    for (int mi = 0; mi < 4; ++mi)
#pragma unroll
        for (int pj = 0; pj < 4; ++pj)
            wmma::fill_fragment(acc[mi][pj], 0.f);

    Pref p;
    ldg_chunk(p, sAh, sAl, sB0h, sB0l, sB1h, sB1l, 0);
    sts_chunk(sm, p, soffA, soffA, soffB1);
    __syncthreads();

    const int NK = Dd / 32;
    for (int kc = 0; kc < NK; ++kc) {
        char* buf = sm + (size_t)(kc & 1) * BUF_B;
        bool pre = (kc + 1 < NK);
        if (pre) ldg_chunk(p, sAh, sAl, sB0h, sB0l, sB1h, sB1l, (kc + 1) * 32);
        mma_chunk64(buf, wm, wn, acc);
        if (pre) sts_chunk(sm + (size_t)((kc + 1) & 1) * BUF_B, p,
                           soffA, soffA, soffB1);
        __syncthreads();
    }

    store_stage(stage, wm, wn, acc);
    __syncthreads();

    // one-shot softmax partial: 2 threads per row, each 128 cols
    {
        int row = tid >> 1;
        const float4* rp = (const float4*)(stage + (size_t)row * STG_P + half * 128);
        const float4* btp = (const float4*)(bts + half * 128);
        float m = -1e30f;
#pragma unroll 8
        for (int j = 0; j < 32; ++j) {
            float4 s4 = rp[j];
            float4 b4 = btp[j];
            s4.x += b4.x; s4.y += b4.y; s4.z += b4.z; s4.w += b4.w;
            m = fmaxf(m, fmaxf(fmaxf(s4.x, s4.y), fmaxf(s4.z, s4.w)));
        }
        m = fmaxf(m, __shfl_xor_sync(0xffffffffu, m, 1));
        float tl = 0.f, ta = 0.f;
        const float4* wp = (const float4*)(ws + half * 128);
#pragma unroll 8
        for (int j = 0; j < 32; ++j) {
            float4 s4 = rp[j];
            float4 b4 = btp[j];
            float4 w4 = wp[j];
            float p0 = __expf(s4.x + b4.x - m);
            float p1 = __expf(s4.y + b4.y - m);
            float p2 = __expf(s4.z + b4.z - m);
            float p3 = __expf(s4.w + b4.w - m);
            tl += (p0 + p1) + (p2 + p3);
            ta += p0 * w4.x + p1 * w4.y + p2 * w4.z + p3 * w4.w;
        }
        tl += __shfl_xor_sync(0xffffffffu, tl, 1);
        ta += __shfl_xor_sync(0xffffffffu, ta, 1);
        if (half == 0) {
            size_t idx = ((size_t)b * Ss + q0 + row) * NSPLIT + split;
            g_pm[idx] = m;
            g_pl[idx] = tl;
            g_pa[idx] = ta;
        }
    }
}

// ---------------------------------------------------------------------------
// combine partials
// ---------------------------------------------------------------------------
__global__ void combine_partials(const float* __restrict__ bo,
                                 float* __restrict__ out)
{
    int r = blockIdx.x * 256 + threadIdx.x;
    const float* pm = g_pm + (size_t)r * NSPLIT;
    const float* pl = g_pl + (size_t)r * NSPLIT;
    const float* pa = g_pa + (size_t)r * NSPLIT;
    float M = -1e30f;
#pragma unroll
    for (int i = 0; i < NSPLIT; ++i) M = fmaxf(M, pm[i]);
    float L = 0.f, A = 0.f;
#pragma unroll
    for (int i = 0; i < NSPLIT; ++i) {
        float f = __expf(pm[i] - M);
        L += pl[i] * f;
        A += pa[i] * f;
    }
    out[r] = A / L + bo[0];
}

// ---------------------------------------------------------------------------
extern "C" void kernel_launch(void* const* d_in, const int* in_sizes, int n_in,
                              void* d_out, int out_size)
{
    const float* x  = (const float*)d_in[0];
    const float* Wq = (const float*)d_in[1];
    const float* bq = (const float*)d_in[2];
    const float* Wk = (const float*)d_in[3];
    const float* bk = (const float*)d_in[4];
    const float* Wv = (const float*)d_in[5];
    const float* bv = (const float*)d_in[6];
    const float* Wo = (const float*)d_in[7];
    const float* bo = (const float*)d_in[8];
    float* out = (float*)d_out;
    (void)bk; (void)in_sizes; (void)n_in; (void)out_size;

    static bool attr_done = false;
    if (!attr_done) {
        cudaFuncSetAttribute(wmma_abt_bf,
                             cudaFuncAttributeMaxDynamicSharedMemorySize, ABT_SMEM);
        cudaFuncSetAttribute(wmma_flash,
                             cudaFuncAttributeMaxDynamicSharedMemorySize, FLASH_SMEM);
        attr_done = true;
    }

    __nv_bfloat16 *xhi, *xlo, *wkhi, *wklo, *wqhi, *wqlo, *mthi, *mtlo, *yhi, *ylo;
    cudaGetSymbolAddress((void**)&xhi, g_xhi);
    cudaGetSymbolAddress((void**)&xlo, g_xlo);
    cudaGetSymbolAddress((void**)&wkhi, g_wkhi);
    cudaGetSymbolAddress((void**)&wklo, g_wklo);
    cudaGetSymbolAddress((void**)&wqhi, g_wqhi);
    cudaGetSymbolAddress((void**)&wqlo, g_wqlo);
    cudaGetSymbolAddress((void**)&mthi, g_mthi);
    cudaGetSymbolAddress((void**)&mtlo, g_mtlo);
    cudaGetSymbolAddress((void**)&yhi, g_yhi);
    cudaGetSymbolAddress((void**)&ylo, g_ylo);
    float *uu, *hh;
    cudaGetSymbolAddress((void**)&uu, g_u);
    cudaGetSymbolAddress((void**)&hh, g_h);

    // splits
    split2<<<(size_t)Mtot * Dd / 2048, 256>>>(x, xhi, xlo);
    split2<<<(size_t)Dd * Dd / 2048, 256>>>(Wk, wkhi, wklo);
    split2<<<(size_t)Dd * Dd / 2048, 256>>>(Wq, wqhi, wqlo);

    // scalars + per-feature vectors
    prep_c<<<1, 256>>>(bv, Wo);
    gemv_row<<<Dd, 256>>>(Wv, Wo, uu);    // u = Wv @ Wo
    gemv_row<<<Dd, 256>>>(Wk, bq, hh);    // h = Wk @ bq
    gemv_row2<<<Mtot, 256>>>(x);          // w = x.u + c ; bt = x.h

    // Mt = Wk @ Wq^T (hi/lo out), then y = x @ Mt^T (hi/lo out)
    {
        dim3 gm(Dd / 256, Dd / 128);
        wmma_abt_bf<<<gm, 256, ABT_SMEM>>>(wkhi, wklo, wqhi, wqlo, mthi, mtlo);
        dim3 gy(Dd / 256, Mtot / 128);
        wmma_abt_bf<<<gy, 256, ABT_SMEM>>>(xhi, xlo, mthi, mtlo, yhi, ylo);
    }

    // t-split flash partials + combine
    dim3 gf(Ss / 128, Bb, NSPLIT);
    wmma_flash<<<gf, 256, FLASH_SMEM>>>();
    combine_partials<<<Mtot / 256, 256>>>(bo, out);
}

// round 13
// speedup vs baseline: 1.3521x; 1.0654x over previous
#include <cuda_runtime.h>
#include <cuda_bf16.h>
#include <mma.h>
#include <cstdint>

using namespace nvcuda;

#define Bb 8
#define Ss 2048
#define Dd 1024
#define Mtot (Bb * Ss)
#define NSPLIT 8
#define MTKS 4                         // k-splits for Mt GEMM

// ---------------------------------------------------------------------------
// Device-global scratch (operands pre-split bf16 hi/lo)
// ---------------------------------------------------------------------------
__device__ __nv_bfloat16 g_xhi[(size_t)Mtot * Dd];
__device__ __nv_bfloat16 g_xlo[(size_t)Mtot * Dd];
__device__ __nv_bfloat16 g_yhi[(size_t)Mtot * Dd];
__device__ __nv_bfloat16 g_ylo[(size_t)Mtot * Dd];
__device__ __nv_bfloat16 g_wkhi[(size_t)Dd * Dd];
__device__ __nv_bfloat16 g_wklo[(size_t)Dd * Dd];
__device__ __nv_bfloat16 g_wqhi[(size_t)Dd * Dd];
__device__ __nv_bfloat16 g_wqlo[(size_t)Dd * Dd];
__device__ __nv_bfloat16 g_mthi[(size_t)Dd * Dd];
__device__ __nv_bfloat16 g_mtlo[(size_t)Dd * Dd];
__device__ float g_mtp[(size_t)MTKS * Dd * Dd];   // Mt k-split partials
__device__ float g_w[Mtot];
__device__ float g_bt[Mtot];
__device__ float g_u[Dd];
__device__ float g_h[Dd];
__device__ float g_c;
__device__ float g_pm[(size_t)Mtot * NSPLIT];
__device__ float g_pl[(size_t)Mtot * NSPLIT];
__device__ float g_pa[(size_t)Mtot * NSPLIT];

// ---------------------------------------------------------------------------
// split2: fp32 -> bf16 hi/lo (elementwise; used for Wk, Wq)
// ---------------------------------------------------------------------------
__global__ void split2(const float* __restrict__ in,
                       __nv_bfloat16* __restrict__ hi,
                       __nv_bfloat16* __restrict__ lo)
{
    size_t i0 = ((size_t)blockIdx.x * 256 + threadIdx.x) * 8;
    float4 a = *(const float4*)(in + i0);
    float4 b = *(const float4*)(in + i0 + 4);
    float v[8] = {a.x, a.y, a.z, a.w, b.x, b.y, b.z, b.w};
    alignas(16) __nv_bfloat16 h[8], l[8];
#pragma unroll
    for (int j = 0; j < 8; ++j) {
        __nv_bfloat16 hh = __float2bfloat16(v[j]);
        h[j] = hh;
        l[j] = __float2bfloat16(v[j] - __bfloat162float(hh));
    }
    *(uint4*)(hi + i0) = *(uint4*)h;
    *(uint4*)(lo + i0) = *(uint4*)l;
}

// ---------------------------------------------------------------------------
// prep kernels
// ---------------------------------------------------------------------------
__global__ void prep_c(const float* __restrict__ bv, const float* __restrict__ Wo)
{
    __shared__ float red[8];
    int tid = threadIdx.x;
    float4 a = ((const float4*)bv)[tid];
    float4 b = ((const float4*)Wo)[tid];
    float s = a.x * b.x + a.y * b.y + a.z * b.z + a.w * b.w;
    #pragma unroll
    for (int off = 16; off; off >>= 1) s += __shfl_xor_sync(0xffffffffu, s, off);
    if ((tid & 31) == 0) red[tid >> 5] = s;
    __syncthreads();
    if (tid < 8) {
        s = red[tid];
        #pragma unroll
        for (int off = 4; off; off >>= 1) s += __shfl_xor_sync(0xffu, s, off);
        if (tid == 0) g_c = s;
    }
}

__global__ void gemv_row(const float* __restrict__ A, const float* __restrict__ vec,
                         float* __restrict__ outv)
{
    __shared__ float red[8];
    int m = blockIdx.x;
    int tid = threadIdx.x;
    float4 a = ((const float4*)(A + (size_t)m * Dd))[tid];
    float4 u = ((const float4*)vec)[tid];
    float s = a.x * u.x + a.y * u.y + a.z * u.z + a.w * u.w;
    #pragma unroll
    for (int off = 16; off; off >>= 1) s += __shfl_xor_sync(0xffffffffu, s, off);
    if ((tid & 31) == 0) red[tid >> 5] = s;
    __syncthreads();
    if (tid < 8) {
        s = red[tid];
        #pragma unroll
        for (int off = 4; off; off >>= 1) s += __shfl_xor_sync(0xffu, s, off);
        if (tid == 0) outv[m] = s;
    }
}

// fused per-row: split x -> xhi/xlo AND w[m] = x.u + c, bt[m] = x.h
__global__ void fused_x(const float* __restrict__ x,
                        __nv_bfloat16* __restrict__ xhi,
                        __nv_bfloat16* __restrict__ xlo)
{
    __shared__ float red1[8], red2[8];
    int m = blockIdx.x;
    int tid = threadIdx.x;
    float4 a = ((const float4*)(x + (size_t)m * Dd))[tid];

    // split 4 elements -> bf16 hi/lo
    {
        float v[4] = {a.x, a.y, a.z, a.w};
        alignas(8) __nv_bfloat16 h[4], l[4];
#pragma unroll
        for (int j = 0; j < 4; ++j) {
            __nv_bfloat16 hh = __float2bfloat16(v[j]);
            h[j] = hh;
            l[j] = __float2bfloat16(v[j] - __bfloat162float(hh));
        }
        size_t o = (size_t)m * Dd + tid * 4;
        *(uint2*)(xhi + o) = *(uint2*)h;
        *(uint2*)(xlo + o) = *(uint2*)l;
    }

    float4 u = ((const float4*)g_u)[tid];
    float4 hv = ((const float4*)g_h)[tid];
    float s1 = a.x * u.x + a.y * u.y + a.z * u.z + a.w * u.w;
    float s2 = a.x * hv.x + a.y * hv.y + a.z * hv.z + a.w * hv.w;
    #pragma unroll
    for (int off = 16; off; off >>= 1) {
        s1 += __shfl_xor_sync(0xffffffffu, s1, off);
        s2 += __shfl_xor_sync(0xffffffffu, s2, off);
    }
    if ((tid & 31) == 0) { red1[tid >> 5] = s1; red2[tid >> 5] = s2; }
    __syncthreads();
    if (tid < 8) {
        s1 = red1[tid]; s2 = red2[tid];
        #pragma unroll
        for (int off = 4; off; off >>= 1) {
            s1 += __shfl_xor_sync(0xffu, s1, off);
            s2 += __shfl_xor_sync(0xffu, s2, off);
        }
        if (tid == 0) { g_w[m] = s1 + g_c; g_bt[m] = s2; }
    }
}

// ---------------------------------------------------------------------------
// wmma machinery: CTA tile 128(m) x 256(n), 8 warps of 64x64, k-chunk 32.
// (validated R12 layout)
// ---------------------------------------------------------------------------
#define TP_E 40
#define A_T_B (128 * 80)
#define B_T_B (256 * 80)
#define OFF_AL A_T_B
#define OFF_BH (2 * A_T_B)
#define OFF_BL (2 * A_T_B + B_T_B)
#define BUF_B  (2 * A_T_B + 2 * B_T_B)
#define STG_P  260
#define STG_B  (128 * STG_P * 4)
#define FL_WS  STG_B
#define FL_BT  (STG_B + 1024)
#define ABT_SMEM   STG_B
#define FLASH_SMEM (STG_B + 2048)

typedef wmma::fragment<wmma::matrix_a, 16, 16, 16, __nv_bfloat16, wmma::row_major> FragA;
typedef wmma::fragment<wmma::matrix_b, 16, 16, 16, __nv_bfloat16, wmma::col_major> FragB;
typedef wmma::fragment<wmma::accumulator, 16, 16, 16, float> FragC;

struct Pref { uint4 r[12]; };

__device__ __forceinline__ void ldg_chunk(Pref& p,
    const __nv_bfloat16* sAh, const __nv_bfloat16* sAl,
    const __nv_bfloat16* sB0h, const __nv_bfloat16* sB0l,
    const __nv_bfloat16* sB1h, const __nv_bfloat16* sB1l, int col)
{
    p.r[0]  = ((const uint4*)(sAh  + col))[0]; p.r[1]  = ((const uint4*)(sAh  + col))[1];
    p.r[2]  = ((const uint4*)(sAl  + col))[0]; p.r[3]  = ((const uint4*)(sAl  + col))[1];
    p.r[4]  = ((const uint4*)(sB0h + col))[0]; p.r[5]  = ((const uint4*)(sB0h + col))[1];
    p.r[6]  = ((const uint4*)(sB0l + col))[0]; p.r[7]  = ((const uint4*)(sB0l + col))[1];
    p.r[8]  = ((const uint4*)(sB1h + col))[0]; p.r[9]  = ((const uint4*)(sB1h + col))[1];
    p.r[10] = ((const uint4*)(sB1l + col))[0]; p.r[11] = ((const uint4*)(sB1l + col))[1];
}

__device__ __forceinline__ void sts_chunk(char* buf, const Pref& p,
                                          uint32_t soffA, uint32_t soffB0,
                                          uint32_t soffB1)
{
    *(uint4*)(buf + soffA)                 = p.r[0];
    *(uint4*)(buf + soffA + 16)            = p.r[1];
    *(uint4*)(buf + OFF_AL + soffA)        = p.r[2];
    *(uint4*)(buf + OFF_AL + soffA + 16)   = p.r[3];
    *(uint4*)(buf + OFF_BH + soffB0)       = p.r[4];
    *(uint4*)(buf + OFF_BH + soffB0 + 16)  = p.r[5];
    *(uint4*)(buf + OFF_BL + soffB0)       = p.r[6];
    *(uint4*)(buf + OFF_BL + soffB0 + 16)  = p.r[7];
    *(uint4*)(buf + OFF_BH + soffB1)       = p.r[8];
    *(uint4*)(buf + OFF_BH + soffB1 + 16)  = p.r[9];
    *(uint4*)(buf + OFF_BL + soffB1)       = p.r[10];
    *(uint4*)(buf + OFF_BL + soffB1 + 16)  = p.r[11];
}

__device__ __forceinline__ void mma_chunk64(const char* buf, int wm, int wn,
                                            FragC (&acc)[4][4])
{
    const __nv_bfloat16* tA  = (const __nv_bfloat16*)(buf);
    const __nv_bfloat16* tAl = (const __nv_bfloat16*)(buf + OFF_AL);
    const __nv_bfloat16* tB  = (const __nv_bfloat16*)(buf + OFF_BH);
    const __nv_bfloat16* tBl = (const __nv_bfloat16*)(buf + OFF_BL);
#pragma unroll
    for (int ks = 0; ks < 2; ++ks) {
        FragA ah[4], al[4];
#pragma unroll
        for (int mi = 0; mi < 4; ++mi) {
            int ro = (64 * wm + 16 * mi) * TP_E + ks * 16;
            wmma::load_matrix_sync(ah[mi], tA + ro, TP_E);
            wmma::load_matrix_sync(al[mi], tAl + ro, TP_E);
        }
#pragma unroll
        for (int pj = 0; pj < 4; ++pj) {
            int ro = (64 * wn + 16 * pj) * TP_E + ks * 16;
            FragB bh, bl;
            wmma::load_matrix_sync(bh, tB + ro, TP_E);
            wmma::load_matrix_sync(bl, tBl + ro, TP_E);
#pragma unroll
            for (int mi = 0; mi < 4; ++mi) {
                wmma::mma_sync(acc[mi][pj], ah[mi], bh, acc[mi][pj]);
                wmma::mma_sync(acc[mi][pj], ah[mi], bl, acc[mi][pj]);
                wmma::mma_sync(acc[mi][pj], al[mi], bh, acc[mi][pj]);
            }
        }
    }
}

__device__ __forceinline__ void store_stage(float* stage, int wm, int wn,
                                            FragC (&acc)[4][4])
{
#pragma unroll
    for (int mi = 0; mi < 4; ++mi)
#pragma unroll
        for (int pj = 0; pj < 4; ++pj)
            wmma::store_matrix_sync(
                stage + (size_t)(64 * wm + 16 * mi) * STG_P + 64 * wn + 16 * pj,
                acc[mi][pj], STG_P, wmma::mem_row_major);
}

// ---------------------------------------------------------------------------
// bf16 A@B^T, full K, hi/lo outputs (used for y = x @ Mt^T)
// ---------------------------------------------------------------------------
__global__ void __launch_bounds__(256, 1)
wmma_abt_bf(const __nv_bfloat16* __restrict__ Ahi, const __nv_bfloat16* __restrict__ Alo,
            const __nv_bfloat16* __restrict__ Bhi, const __nv_bfloat16* __restrict__ Blo,
            __nv_bfloat16* __restrict__ Chi, __nv_bfloat16* __restrict__ Clo)
{
    extern __shared__ char sm[];
    int tid = threadIdx.x;
    int wid = tid >> 5;
    int wm = wid & 1, wn = wid >> 1;
    int m0 = blockIdx.y * 128;
    int n0 = blockIdx.x * 256;

    float* stage = (float*)sm;

    int ra_ = tid >> 1;
    int half = tid & 1;
    uint32_t soffA  = (uint32_t)ra_ * 80 + half * 32;
    uint32_t soffB0 = soffA;
    uint32_t soffB1 = soffA + 128u * 80;
    size_t roA  = (size_t)(m0 + ra_) * Dd + half * 16;
    size_t roB0 = (size_t)(n0 + ra_) * Dd + half * 16;
    size_t roB1 = (size_t)(n0 + 128 + ra_) * Dd + half * 16;
    const __nv_bfloat16* sAh  = Ahi + roA;
    const __nv_bfloat16* sAl  = Alo + roA;
    const __nv_bfloat16* sB0h = Bhi + roB0;
    const __nv_bfloat16* sB0l = Blo + roB0;
    const __nv_bfloat16* sB1h = Bhi + roB1;
    const __nv_bfloat16* sB1l = Blo + roB1;

    FragC acc[4][4];
#pragma unroll
    for (int mi = 0; mi < 4; ++mi)
#pragma unroll
        for (int pj = 0; pj < 4; ++pj)
            wmma::fill_fragment(acc[mi][pj], 0.f);

    Pref p;
    ldg_chunk(p, sAh, sAl, sB0h, sB0l, sB1h, sB1l, 0);
    sts_chunk(sm, p, soffA, soffB0, soffB1);
    __syncthreads();

    const int NK = Dd / 32;
    for (int kc = 0; kc < NK; ++kc) {
        char* buf = sm + (size_t)(kc & 1) * BUF_B;
        bool pre = (kc + 1 < NK);
        if (pre) ldg_chunk(p, sAh, sAl, sB0h, sB0l, sB1h, sB1l, (kc + 1) * 32);
        mma_chunk64(buf, wm, wn, acc);
        if (pre) sts_chunk(sm + (size_t)((kc + 1) & 1) * BUF_B, p,
                           soffA, soffB0, soffB1);
        __syncthreads();
    }

    store_stage(stage, wm, wn, acc);
    __syncthreads();

    int r = tid >> 1;
    int c0 = half * 128;
    const float* sr = stage + (size_t)r * STG_P + c0;
    size_t ob = (size_t)(m0 + r) * Dd + n0 + c0;
#pragma unroll
    for (int j = 0; j < 16; ++j) {
        float4 a = ((const float4*)sr)[2 * j];
        float4 b = ((const float4*)sr)[2 * j + 1];
        float v[8] = {a.x, a.y, a.z, a.w, b.x, b.y, b.z, b.w};
        alignas(16) __nv_bfloat16 h[8], l[8];
#pragma unroll
        for (int q = 0; q < 8; ++q) {
            __nv_bfloat16 hh = __float2bfloat16(v[q]);
            h[q] = hh;
            l[q] = __float2bfloat16(v[q] - __bfloat162float(hh));
        }
        *(uint4*)(Chi + ob + j * 8) = *(uint4*)h;
        *(uint4*)(Clo + ob + j * 8) = *(uint4*)l;
    }
}

// ---------------------------------------------------------------------------
// bf16 A@B^T over K range [z*256, z*256+256), fp32 partial out (Mt k-split)
// grid (Dd/256, Dd/128, MTKS)
// ---------------------------------------------------------------------------
__global__ void __launch_bounds__(256, 1)
wmma_abt_ks(const __nv_bfloat16* __restrict__ Ahi, const __nv_bfloat16* __restrict__ Alo,
            const __nv_bfloat16* __restrict__ Bhi, const __nv_bfloat16* __restrict__ Blo,
            float* __restrict__ Cpart)
{
    extern __shared__ char sm[];
    int tid = threadIdx.x;
    int wid = tid >> 5;
    int wm = wid & 1, wn = wid >> 1;
    int m0 = blockIdx.y * 128;
    int n0 = blockIdx.x * 256;
    int k0 = blockIdx.z * (Dd / MTKS);
    float* C = Cpart + (size_t)blockIdx.z * Dd * Dd;

    float* stage = (float*)sm;

    int ra_ = tid >> 1;
    int half = tid & 1;
    uint32_t soffA  = (uint32_t)ra_ * 80 + half * 32;
    uint32_t soffB0 = soffA;
    uint32_t soffB1 = soffA + 128u * 80;
    size_t roA  = (size_t)(m0 + ra_) * Dd + half * 16 + k0;
    size_t roB0 = (size_t)(n0 + ra_) * Dd + half * 16 + k0;
    size_t roB1 = (size_t)(n0 + 128 + ra_) * Dd + half * 16 + k0;
    const __nv_bfloat16* sAh  = Ahi + roA;
    const __nv_bfloat16* sAl  = Alo + roA;
    const __nv_bfloat16* sB0h = Bhi + roB0;
    const __nv_bfloat16* sB0l = Blo + roB0;
    const __nv_bfloat16* sB1h = Bhi + roB1;
    const __nv_bfloat16* sB1l = Blo + roB1;

    FragC acc[4][4];
#pragma unroll
    for (int mi = 0; mi < 4; ++mi)
#pragma unroll
        for (int pj = 0; pj < 4; ++pj)
            wmma::fill_fragment(acc[mi][pj], 0.f);

    Pref p;
    ldg_chunk(p, sAh, sAl, sB0h, sB0l, sB1h, sB1l, 0);
    sts_chunk(sm, p, soffA, soffB0, soffB1);
    __syncthreads();

    const int NK = (Dd / MTKS) / 32;
    for (int kc = 0; kc < NK; ++kc) {
        char* buf = sm + (size_t)(kc & 1) * BUF_B;
        bool pre = (kc + 1 < NK);
        if (pre) ldg_chunk(p, sAh, sAl, sB0h, sB0l, sB1h, sB1l, (kc + 1) * 32);
        mma_chunk64(buf, wm, wn, acc);
        if (pre) sts_chunk(sm + (size_t)((kc + 1) & 1) * BUF_B, p,
                           soffA, soffB0, soffB1);
        __syncthreads();
    }

    store_stage(stage, wm, wn, acc);
    __syncthreads();

    int r = tid >> 1;
    int c0 = half * 128;
    const float* sr = stage + (size_t)r * STG_P + c0;
    float* cr = C + (size_t)(m0 + r) * Dd + n0 + c0;
#pragma unroll
    for (int j = 0; j < 32; ++j)
        ((float4*)cr)[j] = ((const float4*)sr)[j];
}

// sum MTKS partials, split to bf16 hi/lo
__global__ void mt_reduce(__nv_bfloat16* __restrict__ hi,
                          __nv_bfloat16* __restrict__ lo)
{
    size_t i0 = ((size_t)blockIdx.x * 256 + threadIdx.x) * 4;
    float4 s = *(const float4*)(g_mtp + i0);
#pragma unroll
    for (int z = 1; z < MTKS; ++z) {
        float4 t = *(const float4*)(g_mtp + (size_t)z * Dd * Dd + i0);
        s.x += t.x; s.y += t.y; s.z += t.z; s.w += t.w;
    }
    float v[4] = {s.x, s.y, s.z, s.w};
    alignas(8) __nv_bfloat16 h[4], l[4];
#pragma unroll
    for (int j = 0; j < 4; ++j) {
        __nv_bfloat16 hh = __float2bfloat16(v[j]);
        h[j] = hh;
        l[j] = __float2bfloat16(v[j] - __bfloat162float(hh));
    }
    *(uint2*)(hi + i0) = *(uint2*)h;
    *(uint2*)(lo + i0) = *(uint2*)l;
}

// ---------------------------------------------------------------------------
// wmma flash, t-split (validated R12). grid (Ss/128, Bb, NSPLIT).
// ---------------------------------------------------------------------------
__global__ void __launch_bounds__(256, 1)
wmma_flash()
{
    extern __shared__ char sm[];
    int tid = threadIdx.x;
    int wid = tid >> 5;
    int wm = wid & 1, wn = wid >> 1;
    int b = blockIdx.y;
    int q0 = blockIdx.x * 128;
    int split = blockIdx.z;
    int t0 = split * 256;

    float* stage = (float*)sm;
    float* ws  = (float*)(sm + FL_WS);
    float* bts = (float*)(sm + FL_BT);

    int ra_ = tid >> 1;
    int half = tid & 1;
    uint32_t soffA  = (uint32_t)ra_ * 80 + half * 32;
    uint32_t soffB1 = soffA + 128u * 80;
    size_t roA  = ((size_t)b * Ss + q0 + ra_) * Dd + half * 16;
    size_t roB0 = ((size_t)b * Ss + t0 + ra_) * Dd + half * 16;
    size_t roB1 = ((size_t)b * Ss + t0 + 128 + ra_) * Dd + half * 16;
    const __nv_bfloat16* sAh  = g_yhi + roA;
    const __nv_bfloat16* sAl  = g_ylo + roA;
    const __nv_bfloat16* sB0h = g_xhi + roB0;
    const __nv_bfloat16* sB0l = g_xlo + roB0;
    const __nv_bfloat16* sB1h = g_xhi + roB1;
    const __nv_bfloat16* sB1l = g_xlo + roB1;

    ws[tid]  = g_w[(size_t)b * Ss + t0 + tid];
    bts[tid] = g_bt[(size_t)b * Ss + t0 + tid];

    FragC acc[4][4];
#pragma unroll
    for (int mi = 0; mi < 4; ++mi)
#pragma unroll
        for (int pj = 0; pj < 4; ++pj)
            wmma::fill_fragment(acc[mi][pj], 0.f);

    Pref p;
    ldg_chunk(p, sAh, sAl, sB0h, sB0l, sB1h, sB1l, 0);
    sts_chunk(sm, p, soffA, soffA, soffB1);
    __syncthreads();

    const int NK = Dd / 32;
    for (int kc = 0; kc < NK; ++kc) {
        char* buf = sm + (size_t)(kc & 1) * BUF_B;
        bool pre = (kc + 1 < NK);
        if (pre) ldg_chunk(p, sAh, sAl, sB0h, sB0l, sB1h, sB1l, (kc + 1) * 32);
        mma_chunk64(buf, wm, wn, acc);
        if (pre) sts_chunk(sm + (size_t)((kc + 1) & 1) * BUF_B, p,
                           soffA, soffA, soffB1);
        __syncthreads();
    }

    store_stage(stage, wm, wn, acc);
    __syncthreads();

    // one-shot softmax partial: 2 threads per row, each 128 cols
    {
        int row = tid >> 1;
        const float4* rp = (const float4*)(stage + (size_t)row * STG_P + half * 128);
        const float4* btp = (const float4*)(bts + half * 128);
        float m = -1e30f;
#pragma unroll 8
        for (int j = 0; j < 32; ++j) {
            float4 s4 = rp[j];
            float4 b4 = btp[j];
            s4.x += b4.x; s4.y += b4.y; s4.z += b4.z; s4.w += b4.w;
            m = fmaxf(m, fmaxf(fmaxf(s4.x, s4.y), fmaxf(s4.z, s4.w)));
        }
        m = fmaxf(m, __shfl_xor_sync(0xffffffffu, m, 1));
        float tl = 0.f, ta = 0.f;
        const float4* wp = (const float4*)(ws + half * 128);
#pragma unroll 8
        for (int j = 0; j < 32; ++j) {
            float4 s4 = rp[j];
            float4 b4 = btp[j];
            float4 w4 = wp[j];
            float p0 = __expf(s4.x + b4.x - m);
            float p1 = __expf(s4.y + b4.y - m);
            float p2 = __expf(s4.z + b4.z - m);
            float p3 = __expf(s4.w + b4.w - m);
            tl += (p0 + p1) + (p2 + p3);
            ta += p0 * w4.x + p1 * w4.y + p2 * w4.z + p3 * w4.w;
        }
        tl += __shfl_xor_sync(0xffffffffu, tl, 1);
        ta += __shfl_xor_sync(0xffffffffu, ta, 1);
        if (half == 0) {
            size_t idx = ((size_t)b * Ss + q0 + row) * NSPLIT + split;
            g_pm[idx] = m;
            g_pl[idx] = tl;
            g_pa[idx] = ta;
        }
    }
}

// ---------------------------------------------------------------------------
// combine partials
// ---------------------------------------------------------------------------
__global__ void combine_partials(const float* __restrict__ bo,
                                 float* __restrict__ out)
{
    int r = blockIdx.x * 256 + threadIdx.x;
    const float* pm = g_pm + (size_t)r * NSPLIT;
    const float* pl = g_pl + (size_t)r * NSPLIT;
    const float* pa = g_pa + (size_t)r * NSPLIT;
    float M = -1e30f;
#pragma unroll
    for (int i = 0; i < NSPLIT; ++i) M = fmaxf(M, pm[i]);
    float L = 0.f, A = 0.f;
#pragma unroll
    for (int i = 0; i < NSPLIT; ++i) {
        float f = __expf(pm[i] - M);
        L += pl[i] * f;
        A += pa[i] * f;
    }
    out[r] = A / L + bo[0];
}

// ---------------------------------------------------------------------------
extern "C" void kernel_launch(void* const* d_in, const int* in_sizes, int n_in,
                              void* d_out, int out_size)
{
    const float* x  = (const float*)d_in[0];
    const float* Wq = (const float*)d_in[1];
    const float* bq = (const float*)d_in[2];
    const float* Wk = (const float*)d_in[3];
    const float* bk = (const float*)d_in[4];
    const float* Wv = (const float*)d_in[5];
    const float* bv = (const float*)d_in[6];
    const float* Wo = (const float*)d_in[7];
    const float* bo = (const float*)d_in[8];
    float* out = (float*)d_out;
    (void)bk; (void)in_sizes; (void)n_in; (void)out_size;

    static bool attr_done = false;
    if (!attr_done) {
        cudaFuncSetAttribute(wmma_abt_bf,
                             cudaFuncAttributeMaxDynamicSharedMemorySize, ABT_SMEM);
        cudaFuncSetAttribute(wmma_abt_ks,
                             cudaFuncAttributeMaxDynamicSharedMemorySize, ABT_SMEM);
        cudaFuncSetAttribute(wmma_flash,
                             cudaFuncAttributeMaxDynamicSharedMemorySize, FLASH_SMEM);
        attr_done = true;
    }

    __nv_bfloat16 *xhi, *xlo, *wkhi, *wklo, *wqhi, *wqlo, *mthi, *mtlo, *yhi, *ylo;
    cudaGetSymbolAddress((void**)&xhi, g_xhi);
    cudaGetSymbolAddress((void**)&xlo, g_xlo);
    cudaGetSymbolAddress((void**)&wkhi, g_wkhi);
    cudaGetSymbolAddress((void**)&wklo, g_wklo);
    cudaGetSymbolAddress((void**)&wqhi, g_wqhi);
    cudaGetSymbolAddress((void**)&wqlo, g_wqlo);
    cudaGetSymbolAddress((void**)&mthi, g_mthi);
    cudaGetSymbolAddress((void**)&mtlo, g_mtlo);
    cudaGetSymbolAddress((void**)&yhi, g_yhi);
    cudaGetSymbolAddress((void**)&ylo, g_ylo);
    float *uu, *hh, *mtp;
    cudaGetSymbolAddress((void**)&uu, g_u);
    cudaGetSymbolAddress((void**)&hh, g_h);
    cudaGetSymbolAddress((void**)&mtp, g_mtp);

    // weight splits (tiny)
    split2<<<(size_t)Dd * Dd / 2048, 256>>>(Wk, wkhi, wklo);
    split2<<<(size_t)Dd * Dd / 2048, 256>>>(Wq, wqhi, wqlo);

    // scalars + per-feature vectors, then fused x split + w/bt GEMVs
    prep_c<<<1, 256>>>(bv, Wo);
    gemv_row<<<Dd, 256>>>(Wv, Wo, uu);    // u = Wv @ Wo
    gemv_row<<<Dd, 256>>>(Wk, bq, hh);    // h = Wk @ bq
    fused_x<<<Mtot, 256>>>(x, xhi, xlo);  // xhi/xlo + w + bt in one x pass

    // Mt = Wk @ Wq^T with k-split 4 -> reduce+split, then y = x @ Mt^T
    {
        dim3 gm(Dd / 256, Dd / 128, MTKS);
        wmma_abt_ks<<<gm, 256, ABT_SMEM>>>(wkhi, wklo, wqhi, wqlo, mtp);
        mt_reduce<<<(size_t)Dd * Dd / 1024, 256>>>(mthi, mtlo);
        dim3 gy(Dd / 256, Mtot / 128);
        wmma_abt_bf<<<gy, 256, ABT_SMEM>>>(xhi, xlo, mthi, mtlo, yhi, ylo);
    }

    // t-split flash partials + combine
    dim3 gf(Ss / 128, Bb, NSPLIT);
    wmma_flash<<<gf, 256, FLASH_SMEM>>>();
    combine_partials<<<Mtot / 256, 256>>>(bo, out);
}